// round 14
// baseline (speedup 1.0000x reference)
#include <cuda_runtime.h>
#include <cuda_bf16.h>
#include <cuda_fp16.h>
#include <cstdint>
#include <math.h>

// ---------------------------------------------------------------------------
// Problem constants
// ---------------------------------------------------------------------------
#define B_  2
#define T_  2048
#define E_  128
#define H_  8
#define HS_ 16
#define HID_ 65536
#define NTOK (B_ * T_)          // 4096
#define EPS_ 1e-5f
#define ATT_SCALE 0.08838834764831845f   // 1/sqrt(128)

// FFN tiling (1-pass fp16, JC=64, 256 threads, 2 CTAs/SM)  [R13 winner, frozen]
#define FFN_M 128
#define JC2 64
#define NCHUNK2 (HID_ / JC2)        // 1024
#define NTILE (NTOK / FFN_M)        // 32
#define TOT2 (NTILE * NCHUNK2)      // 32768
#define FFN_GRID 888

#define SH   136
#define SWN  72
#define SW2  136

#define G3_H 0
#define G3_W1 34816
#define G3_W2(b) (53248 + (b) * 17408)
#define G3_AC 88064
#define FFN_SMEM4 106496

// QKV / OPROJ fp16 1-pass smem
#define GH_A 0                     // 64 x SH x 2 = 17408
#define GH_W 17408                 // 128 x SH x 2 = 34816
#define QKV_SMEM_H 52224
#define OP_X2T_H 52224             // 64 x 132 x 4 = 33792
#define OP_SMEM_H 86016

// Attention smem (dynamic): 4 K buffers + 4 V buffers, 128x16 fp32 each
#define AT_K(b) ((b) * 8192)
#define AT_V(b) (32768 + (b) * 8192)
#define AT_SMEM 65536

// ---------------------------------------------------------------------------
// PTX helpers
// ---------------------------------------------------------------------------
__device__ __forceinline__ uint32_t smem_u32(const void* p) {
    uint32_t a;
    asm("{ .reg .u64 t; cvta.to.shared.u64 t, %1; cvt.u32.u64 %0, t; }"
        : "=r"(a) : "l"(p));
    return a;
}
__device__ __forceinline__ void ldsm4(uint32_t a[4], uint32_t addr) {
    asm volatile("ldmatrix.sync.aligned.m8n8.x4.shared.b16 {%0,%1,%2,%3}, [%4];"
                 : "=r"(a[0]), "=r"(a[1]), "=r"(a[2]), "=r"(a[3]) : "r"(addr));
}
__device__ __forceinline__ void ldsm4t(uint32_t a[4], uint32_t addr) {
    asm volatile("ldmatrix.sync.aligned.m8n8.x4.trans.shared.b16 {%0,%1,%2,%3}, [%4];"
                 : "=r"(a[0]), "=r"(a[1]), "=r"(a[2]), "=r"(a[3]) : "r"(addr));
}
__device__ __forceinline__ void mma16816h(float c[4], const uint32_t a[4],
                                          const uint32_t b[2]) {
    asm volatile("mma.sync.aligned.m16n8k16.row.col.f32.f16.f16.f32 "
                 "{%0,%1,%2,%3}, {%4,%5,%6,%7}, {%8,%9}, {%0,%1,%2,%3};"
                 : "+f"(c[0]), "+f"(c[1]), "+f"(c[2]), "+f"(c[3])
                 : "r"(a[0]), "r"(a[1]), "r"(a[2]), "r"(a[3]),
                   "r"(b[0]), "r"(b[1]));
}
__device__ __forceinline__ void cp16(uint32_t s, const void* g) {
    asm volatile("cp.async.cg.shared.global [%0], [%1], 16;" :: "r"(s), "l"(g));
}
#define CP_COMMIT() asm volatile("cp.async.commit_group;" ::: "memory")
#define CP_WAIT1()  asm volatile("cp.async.wait_group 1;" ::: "memory")
#define CP_WAIT0()  asm volatile("cp.async.wait_group 0;" ::: "memory")

__device__ __forceinline__ uint32_t pack_f16(float a, float b) {
    __half2 h = __floats2half2_rn(a, b);
    return *reinterpret_cast<uint32_t*>(&h);
}

// ---------------------------------------------------------------------------
// Scratch
// ---------------------------------------------------------------------------
__device__ float g_q  [B_ * H_ * T_ * HS_];
__device__ float g_k  [B_ * H_ * T_ * HS_];
__device__ float g_v  [B_ * H_ * T_ * HS_];
__device__ float g_x2 [NTOK * E_];
__device__ float g_part2[2 * FFN_GRID * FFN_M * E_];
__device__ __half g_h1f [NTOK * E_];
__device__ __half g_aof [NTOK * E_];
__device__ __half g_h2f [NTOK * E_];
__device__ __half g_w1f [E_ * HID_];
__device__ __half g_w2f [HID_ * E_];
__device__ __half g_wqkvf[E_ * 384];
__device__ __half g_wof [E_ * E_];

// ---------------------------------------------------------------------------
// fp32 -> fp16 convert
// ---------------------------------------------------------------------------
__global__ void k_cvthalf(const float* __restrict__ src,
                          __half* __restrict__ dst, int n4) {
    int i = blockIdx.x * 256 + threadIdx.x;
    if (i >= n4) return;
    float4 v = ((const float4*)src)[i];
    uint2 o;
    o.x = pack_f16(v.x, v.y);
    o.y = pack_f16(v.z, v.w);
    ((uint2*)dst)[i] = o;
}

// Build Wqkv [E][384] fp16 from Wq/Wk/Wv [H][E][HS]
__global__ void k_prep_wqkv_h(const float* __restrict__ Wq, const float* __restrict__ Wk,
                              const float* __restrict__ Wv, __half* __restrict__ o) {
    int idx = blockIdx.x * 256 + threadIdx.x;
    if (idx >= E_ * 384) return;
    int e = idx / 384, n = idx % 384;
    int which = n >> 7, r = n & 127, h = r >> 4, hd = r & 15;
    const float* W = (which == 0) ? Wq : (which == 1) ? Wk : Wv;
    o[idx] = __float2half_rn(W[((size_t)h * E_ + e) * HS_ + hd]);
}

// ---------------------------------------------------------------------------
// LayerNorm with fp16 output (LN1)
// ---------------------------------------------------------------------------
__global__ void k_ln_half(const float* __restrict__ x, const float* __restrict__ g,
                          const float* __restrict__ b, __half* __restrict__ of) {
    int t = blockIdx.x * 4 + (threadIdx.x >> 5);
    int lane = threadIdx.x & 31;
    float4 a = ((const float4*)(x + (size_t)t * E_))[lane];

    float s = a.x + a.y + a.z + a.w;
    #pragma unroll
    for (int o = 16; o; o >>= 1) s += __shfl_xor_sync(0xffffffffu, s, o);
    float mu = s * (1.0f / E_);

    float dx = a.x - mu, dy = a.y - mu, dz = a.z - mu, dw = a.w - mu;
    float v = dx*dx + dy*dy + dz*dz + dw*dw;
    #pragma unroll
    for (int o = 16; o; o >>= 1) v += __shfl_xor_sync(0xffffffffu, v, o);
    float rs = rsqrtf(v * (1.0f / E_) + EPS_);

    float4 gg = ((const float4*)g)[lane];
    float4 bb = ((const float4*)b)[lane];
    uint2 hp;
    hp.x = pack_f16(dx * rs * gg.x + bb.x, dy * rs * gg.y + bb.y);
    hp.y = pack_f16(dz * rs * gg.z + bb.z, dw * rs * gg.w + bb.w);
    ((uint2*)(of + (size_t)t * E_))[lane] = hp;
}

// ---------------------------------------------------------------------------
// QKV via fp16 1-pass mma: grid (NTOK/64, 3 slabs), 256 thr
// ---------------------------------------------------------------------------
__global__ void __launch_bounds__(256, 1)
k_qkv_h(const __half* __restrict__ af, const __half* __restrict__ wf,
        float* __restrict__ q, float* __restrict__ k, float* __restrict__ v) {
    extern __shared__ char smem[];
    const uint32_t sb = smem_u32(smem);
    const int tid = threadIdx.x, wid = tid >> 5, lane = tid & 31;
    const int gid = lane >> 2, tig = lane & 3;
    const int lrow = (lane & 7) + ((lane >> 3) & 1) * 8;
    const int lcol = ((lane >> 4) & 1) * 8;
    const int wm = wid & 1, wn = wid >> 1;
    const int tok0 = blockIdx.x * 64;
    const int slab = blockIdx.y;
    const int m0 = wm * 32, n0 = wn * 32;

    for (int i = tid; i < 1024; i += 256) {
        int r = i >> 4, s = i & 15;
        *(float4*)(smem + GH_A + (r * SH + s * 8) * 2) =
            *(const float4*)(af + (size_t)(tok0 + r) * E_ + s * 8);
    }
    for (int i = tid; i < 2048; i += 256) {
        int r = i >> 4, s = i & 15;
        *(float4*)(smem + GH_W + (r * SH + s * 8) * 2) =
            *(const float4*)(wf + (size_t)r * 384 + slab * 128 + s * 8);
    }
    __syncthreads();

    float acc[2][4][4];
    #pragma unroll
    for (int a = 0; a < 2; ++a)
        #pragma unroll
        for (int b = 0; b < 4; ++b)
            #pragma unroll
            for (int c = 0; c < 4; ++c) acc[a][b][c] = 0.f;

    #pragma unroll
    for (int kf = 0; kf < 8; ++kf) {
        const int k0 = kf * 16;
        uint32_t afr[2][4], bq[2][4];
        #pragma unroll
        for (int mi = 0; mi < 2; ++mi) {
            uint32_t ro = (uint32_t)((m0 + mi * 16 + lrow) * SH + k0 + lcol) * 2;
            ldsm4(afr[mi], sb + GH_A + ro);
        }
        #pragma unroll
        for (int g = 0; g < 2; ++g) {
            uint32_t ro = (uint32_t)((k0 + lrow) * SH + n0 + g * 16 + lcol) * 2;
            ldsm4t(bq[g], sb + GH_W + ro);
        }
        #pragma unroll
        for (int mi = 0; mi < 2; ++mi)
            #pragma unroll
            for (int g = 0; g < 2; ++g)
                #pragma unroll
                for (int hh = 0; hh < 2; ++hh)
                    mma16816h(acc[mi][g * 2 + hh], afr[mi], &bq[g][hh * 2]);
    }

    float* dst = (slab == 0) ? q : (slab == 1) ? k : v;
    #pragma unroll
    for (int mi = 0; mi < 2; ++mi) {
        int tg = tok0 + m0 + mi * 16 + gid;
        int b = tg >> 11, tl = tg & 2047;
        #pragma unroll
        for (int ni = 0; ni < 4; ++ni) {
            int n = n0 + ni * 8 + tig * 2;
            int h = n >> 4, hd = n & 15;
            float* p = dst + (((size_t)(b * 8 + h)) * T_ + tl) * HS_ + hd;
            *(float2*)p = make_float2(acc[mi][ni][0], acc[mi][ni][1]);
            *(float2*)(p + 8 * HS_) = make_float2(acc[mi][ni][2], acc[mi][ni][3]);
        }
    }
}

// ---------------------------------------------------------------------------
// Attention v3: grid (16,16) heavy-first, 256 thr, 2-way K-split + merge.
// Warp w: query subgroup wq = w>>1 (32 queries), split s = w&1.
// Phase p stages tiles {2p, 2p+1}; split s computes tile 2p+s.
// ---------------------------------------------------------------------------
__global__ void __launch_bounds__(256, 1)
k_attn3(const float* __restrict__ q, const float* __restrict__ k,
        const float* __restrict__ v, __half* __restrict__ aof) {
    extern __shared__ char smem[];
    const uint32_t sbase = smem_u32(smem);
    const int tid = threadIdx.x, wid = tid >> 5, lane = tid & 31;
    const int qblk = 15 - blockIdx.x;          // heavy CTAs first
    const int bh = blockIdx.y;
    const int wq = wid >> 1, s = wid & 1;
    const int t = qblk * 128 + wq * 32 + lane;
    const int ntiles = qblk + 1;

    const float* qp = q + ((size_t)bh * T_ + t) * HS_;
    float4 q0 = ((const float4*)qp)[0];
    float4 q1 = ((const float4*)qp)[1];
    float4 q2 = ((const float4*)qp)[2];
    float4 q3 = ((const float4*)qp)[3];
    const float* kb_ = k + (size_t)bh * T_ * HS_;
    const float* vb_ = v + (size_t)bh * T_ * HS_;

    float m = -1e30f, l = 0.f;
    float o[16];
    #pragma unroll
    for (int d = 0; d < 16; ++d) o[d] = 0.f;

    // prefetch tiles 0,1
    #pragma unroll
    for (int pre = 0; pre < 2; ++pre) {
        if (pre < ntiles) {
            int kb2 = pre * 128;
            #pragma unroll
            for (int i = 0; i < 2; ++i) {
                int f = tid + i * 256;
                int row = f >> 2, sg = f & 3;
                cp16(sbase + AT_K(pre) + row * 64 + sg * 16,
                     kb_ + (size_t)(kb2 + row) * HS_ + sg * 4);
                cp16(sbase + AT_V(pre) + row * 64 + sg * 16,
                     vb_ + (size_t)(kb2 + row) * HS_ + sg * 4);
            }
        }
    }
    CP_COMMIT();

    const int nphase = (ntiles + 1) >> 1;
    for (int p = 0; p < nphase; ++p) {
        // prefetch pair {2p+2, 2p+3}
        #pragma unroll
        for (int pre = 0; pre < 2; ++pre) {
            int tl2 = 2 * p + 2 + pre;
            if (tl2 < ntiles) {
                int buf = tl2 & 3;
                int kb2 = tl2 * 128;
                #pragma unroll
                for (int i = 0; i < 2; ++i) {
                    int f = tid + i * 256;
                    int row = f >> 2, sg = f & 3;
                    cp16(sbase + AT_K(buf) + row * 64 + sg * 16,
                         kb_ + (size_t)(kb2 + row) * HS_ + sg * 4);
                    cp16(sbase + AT_V(buf) + row * 64 + sg * 16,
                         vb_ + (size_t)(kb2 + row) * HS_ + sg * 4);
                }
            }
        }
        CP_COMMIT();
        CP_WAIT1();
        __syncthreads();

        const int mytile = 2 * p + s;
        if (mytile < ntiles) {
            const int buf = mytile & 3;
            const int kbase = mytile * 128;
            const float* Kb = (const float*)(smem + AT_K(buf));
            const float* Vb = (const float*)(smem + AT_V(buf));
            #pragma unroll 2
            for (int j = 0; j < 128; ++j) {
                const float4* kr = (const float4*)(Kb + j * 16);
                float4 k0 = kr[0], k1 = kr[1], k2 = kr[2], k3 = kr[3];
                float sc = q0.x*k0.x + q0.y*k0.y + q0.z*k0.z + q0.w*k0.w
                         + q1.x*k1.x + q1.y*k1.y + q1.z*k1.z + q1.w*k1.w
                         + q2.x*k2.x + q2.y*k2.y + q2.z*k2.z + q2.w*k2.w
                         + q3.x*k3.x + q3.y*k3.y + q3.z*k3.z + q3.w*k3.w;
                sc *= ATT_SCALE;
                if (kbase + j > t) sc = -1e30f;
                float mn = fmaxf(m, sc);
                float scale = __expf(m - mn);
                float w = __expf(sc - mn);
                l = l * scale + w;
                const float4* vr = (const float4*)(Vb + j * 16);
                float4 v0 = vr[0], v1 = vr[1], v2 = vr[2], v3 = vr[3];
                o[0]  = o[0]*scale  + w*v0.x;  o[1]  = o[1]*scale  + w*v0.y;
                o[2]  = o[2]*scale  + w*v0.z;  o[3]  = o[3]*scale  + w*v0.w;
                o[4]  = o[4]*scale  + w*v1.x;  o[5]  = o[5]*scale  + w*v1.y;
                o[6]  = o[6]*scale  + w*v1.z;  o[7]  = o[7]*scale  + w*v1.w;
                o[8]  = o[8]*scale  + w*v2.x;  o[9]  = o[9]*scale  + w*v2.y;
                o[10] = o[10]*scale + w*v2.z;  o[11] = o[11]*scale + w*v2.w;
                o[12] = o[12]*scale + w*v3.x;  o[13] = o[13]*scale + w*v3.y;
                o[14] = o[14]*scale + w*v3.z;  o[15] = o[15]*scale + w*v3.w;
                m = mn;
            }
        }
        __syncthreads();
    }

    // merge split states (split 1 -> smem -> split 0 merges)
    float* st = (float*)smem + (wq * 32 + lane) * 18;
    if (s == 1) {
        st[0] = m; st[1] = l;
        #pragma unroll
        for (int d = 0; d < 16; ++d) st[2 + d] = o[d];
    }
    __syncthreads();
    if (s == 0) {
        float m1 = st[0], l1 = st[1];
        float mn = fmaxf(m, m1);
        float s0 = __expf(m - mn), s1 = __expf(m1 - mn);
        l = l * s0 + l1 * s1;
        float inv = 1.0f / l;
        int b = bh >> 3, h = bh & 7;
        size_t base = ((size_t)b * T_ + t) * E_ + h * HS_;
        uint32_t hp[8];
        #pragma unroll
        for (int d = 0; d < 8; ++d) {
            float f0 = (o[2*d]     * s0 + st[2 + 2*d]     * s1) * inv;
            float f1 = (o[2*d + 1] * s0 + st[2 + 2*d + 1] * s1) * inv;
            hp[d] = pack_f16(f0, f1);
        }
        ((uint4*)(aof + base))[0] = make_uint4(hp[0], hp[1], hp[2], hp[3]);
        ((uint4*)(aof + base))[1] = make_uint4(hp[4], hp[5], hp[6], hp[7]);
    }
}

// ---------------------------------------------------------------------------
// O-proj fp16 1-pass + residual + fused LN2 (h2 fp16 out)
// ---------------------------------------------------------------------------
__global__ void __launch_bounds__(256, 1)
k_oproj_h(const __half* __restrict__ af, const __half* __restrict__ wf,
          const float* __restrict__ bo, const float* __restrict__ x,
          const float* __restrict__ g2, const float* __restrict__ be2,
          float* __restrict__ x2, __half* __restrict__ h2f) {
    extern __shared__ char smem[];
    const uint32_t sb = smem_u32(smem);
    float* x2t = (float*)(smem + OP_X2T_H);
    const int tid = threadIdx.x, wid = tid >> 5, lane = tid & 31;
    const int gid = lane >> 2, tig = lane & 3;
    const int lrow = (lane & 7) + ((lane >> 3) & 1) * 8;
    const int lcol = ((lane >> 4) & 1) * 8;
    const int wm = wid & 1, wn = wid >> 1;
    const int tok0 = blockIdx.x * 64;
    const int m0 = wm * 32, n0 = wn * 32;

    for (int i = tid; i < 1024; i += 256) {
        int r = i >> 4, s = i & 15;
        *(float4*)(smem + GH_A + (r * SH + s * 8) * 2) =
            *(const float4*)(af + (size_t)(tok0 + r) * E_ + s * 8);
    }
    for (int i = tid; i < 2048; i += 256) {
        int r = i >> 4, s = i & 15;
        *(float4*)(smem + GH_W + (r * SH + s * 8) * 2) =
            *(const float4*)(wf + (size_t)r * E_ + s * 8);
    }
    __syncthreads();

    float acc[2][4][4];
    #pragma unroll
    for (int a = 0; a < 2; ++a)
        #pragma unroll
        for (int b = 0; b < 4; ++b)
            #pragma unroll
            for (int c = 0; c < 4; ++c) acc[a][b][c] = 0.f;

    #pragma unroll
    for (int kf = 0; kf < 8; ++kf) {
        const int k0 = kf * 16;
        uint32_t afr[2][4], bq[2][4];
        #pragma unroll
        for (int mi = 0; mi < 2; ++mi) {
            uint32_t ro = (uint32_t)((m0 + mi * 16 + lrow) * SH + k0 + lcol) * 2;
            ldsm4(afr[mi], sb + GH_A + ro);
        }
        #pragma unroll
        for (int g = 0; g < 2; ++g) {
            uint32_t ro = (uint32_t)((k0 + lrow) * SH + n0 + g * 16 + lcol) * 2;
            ldsm4t(bq[g], sb + GH_W + ro);
        }
        #pragma unroll
        for (int mi = 0; mi < 2; ++mi)
            #pragma unroll
            for (int g = 0; g < 2; ++g)
                #pragma unroll
                for (int hh = 0; hh < 2; ++hh)
                    mma16816h(acc[mi][g * 2 + hh], afr[mi], &bq[g][hh * 2]);
    }

    #pragma unroll
    for (int mi = 0; mi < 2; ++mi) {
        int rl = m0 + mi * 16 + gid;
        #pragma unroll
        for (int ni = 0; ni < 4; ++ni) {
            int col = n0 + ni * 8 + tig * 2;
            float2 bia = *(const float2*)(bo + col);
            float2 xr0 = *(const float2*)(x + (size_t)(tok0 + rl) * E_ + col);
            float2 xr1 = *(const float2*)(x + (size_t)(tok0 + rl + 8) * E_ + col);
            x2t[rl * 132 + col]           = acc[mi][ni][0] + bia.x + xr0.x;
            x2t[rl * 132 + col + 1]       = acc[mi][ni][1] + bia.y + xr0.y;
            x2t[(rl + 8) * 132 + col]     = acc[mi][ni][2] + bia.x + xr1.x;
            x2t[(rl + 8) * 132 + col + 1] = acc[mi][ni][3] + bia.y + xr1.y;
        }
    }
    __syncthreads();

    float4 gg = ((const float4*)g2)[lane];
    float4 bb = ((const float4*)be2)[lane];
    #pragma unroll
    for (int r = 0; r < 8; ++r) {
        int tokl = wid * 8 + r;
        float4 a = *(float4*)(x2t + tokl * 132 + lane * 4);
        float s = a.x + a.y + a.z + a.w;
        #pragma unroll
        for (int o = 16; o; o >>= 1) s += __shfl_xor_sync(0xffffffffu, s, o);
        float mu = s * (1.0f / E_);
        float dx = a.x - mu, dy = a.y - mu, dz = a.z - mu, dw = a.w - mu;
        float vv = dx*dx + dy*dy + dz*dz + dw*dw;
        #pragma unroll
        for (int o = 16; o; o >>= 1) vv += __shfl_xor_sync(0xffffffffu, vv, o);
        float rs = rsqrtf(vv * (1.0f / E_) + EPS_);

        ((float4*)(x2 + (size_t)(tok0 + tokl) * E_))[lane] = a;

        uint2 hp;
        hp.x = pack_f16(dx * rs * gg.x + bb.x, dy * rs * gg.y + bb.y);
        hp.y = pack_f16(dz * rs * gg.z + bb.z, dw * rs * gg.w + bb.w);
        ((uint2*)(h2f + (size_t)(tok0 + tokl) * E_))[lane] = hp;
    }
}

// ---------------------------------------------------------------------------
// FFN (R13 winner, frozen): fp16 1-pass, JC=64, 256 thr, 2 CTAs/SM
// ---------------------------------------------------------------------------
__global__ void __launch_bounds__(256, 2)
k_ffn4(const __half* __restrict__ h2,
       const __half* __restrict__ w1, const __half* __restrict__ w2,
       const float* __restrict__ bf1, float* __restrict__ partial) {
    extern __shared__ char smem[];
    const uint32_t sb = smem_u32(smem);
    const int tid = threadIdx.x, wid = tid >> 5, lane = tid & 31;
    const int gid = lane >> 2, tig = lane & 3;
    const int lrow = (lane & 7) + ((lane >> 3) & 1) * 8;
    const int lcol = ((lane >> 4) & 1) * 8;
    const int wm = wid & 3, wn = wid >> 2;
    const int m0 = wm * 32;
    const int cta = blockIdx.x;
    const int u0 = (int)(((long long)cta * TOT2) / FFN_GRID);
    const int u1 = (int)(((long long)(cta + 1) * TOT2) / FFN_GRID);

    {
        int jb = (u0 & (NCHUNK2 - 1)) * JC2;
        #pragma unroll
        for (int i = 0; i < 4; ++i) {
            int t = tid + i * 256;
            int e = t >> 3, sg = t & 7;
            cp16(sb + G3_W1 + (e * SWN + sg * 8) * 2, w1 + (size_t)e * HID_ + jb + sg * 8);
            int j = t >> 4, sg2 = t & 15;
            cp16(sb + G3_W2(0) + (j * SW2 + sg2 * 8) * 2, w2 + (size_t)(jb + j) * E_ + sg2 * 8);
        }
    }
    CP_COMMIT();

    int u = u0, seg = 0;
    while (u < u1) {
        const int tile = u >> 10;
        const int useg_end = min(u1, (tile + 1) << 10);
        const int tok0 = tile * FFN_M;

        for (int i = tid; i < 2048; i += 256) {
            int r = i >> 4, s = i & 15;
            *(float4*)(smem + G3_H + (r * SH + s * 8) * 2) =
                *(const float4*)(h2 + (size_t)(tok0 + r) * E_ + s * 8);
        }
        float acc2[2][8][4];
        #pragma unroll
        for (int a = 0; a < 2; ++a)
            #pragma unroll
            for (int b = 0; b < 8; ++b)
                #pragma unroll
                for (int c = 0; c < 4; ++c) acc2[a][b][c] = 0.f;
        __syncthreads();

        for (; u < useg_end; ++u) {
            const int buf = (u - u0) & 1;
            const int jb = (u & (NCHUNK2 - 1)) * JC2;
            const bool more = (u + 1 < u1);

            if (more) {
                int jn = ((u + 1) & (NCHUNK2 - 1)) * JC2;
                #pragma unroll
                for (int i = 0; i < 4; ++i) {
                    int t = tid + i * 256;
                    int j = t >> 4, sg2 = t & 15;
                    cp16(sb + G3_W2(buf ^ 1) + (j * SW2 + sg2 * 8) * 2,
                         w2 + (size_t)(jn + j) * E_ + sg2 * 8);
                }
                CP_COMMIT();
                CP_WAIT1();
            } else {
                CP_WAIT0();
            }
            __syncthreads();

            const int n1 = wn * 32;
            float acc1[2][4][4];
            #pragma unroll
            for (int a = 0; a < 2; ++a)
                #pragma unroll
                for (int b = 0; b < 4; ++b)
                    #pragma unroll
                    for (int d = 0; d < 4; ++d) acc1[a][b][d] = 0.f;

            #pragma unroll
            for (int kf = 0; kf < 8; ++kf) {
                const int k0 = kf * 16;
                uint32_t af[2][4], bq[2][4];
                #pragma unroll
                for (int mi = 0; mi < 2; ++mi) {
                    uint32_t ro = (uint32_t)((m0 + mi * 16 + lrow) * SH + k0 + lcol) * 2;
                    ldsm4(af[mi], sb + G3_H + ro);
                }
                #pragma unroll
                for (int g = 0; g < 2; ++g) {
                    uint32_t ro = (uint32_t)((k0 + lrow) * SWN + n1 + g * 16 + lcol) * 2;
                    ldsm4t(bq[g], sb + G3_W1 + ro);
                }
                #pragma unroll
                for (int mi = 0; mi < 2; ++mi)
                    #pragma unroll
                    for (int g = 0; g < 2; ++g)
                        #pragma unroll
                        for (int hh = 0; hh < 2; ++hh)
                            mma16816h(acc1[mi][g * 2 + hh], af[mi], &bq[g][hh * 2]);
            }

            #pragma unroll
            for (int ni = 0; ni < 4; ++ni) {
                const int col = n1 + ni * 8 + tig * 2;
                const float2 bia = *(const float2*)(bf1 + jb + col);
                #pragma unroll
                for (int mi = 0; mi < 2; ++mi) {
                    const int row = m0 + mi * 16 + gid;
                    float a0 = fmaxf(acc1[mi][ni][0] + bia.x, 0.f);
                    float a1 = fmaxf(acc1[mi][ni][1] + bia.y, 0.f);
                    float a2 = fmaxf(acc1[mi][ni][2] + bia.x, 0.f);
                    float a3 = fmaxf(acc1[mi][ni][3] + bia.y, 0.f);
                    *(uint32_t*)(smem + G3_AC + (uint32_t)(row * SWN + col) * 2) =
                        pack_f16(a0, a1);
                    *(uint32_t*)(smem + G3_AC + (uint32_t)((row + 8) * SWN + col) * 2) =
                        pack_f16(a2, a3);
                }
            }
            __syncthreads();

            if (more) {
                int jn = ((u + 1) & (NCHUNK2 - 1)) * JC2;
                #pragma unroll
                for (int i = 0; i < 4; ++i) {
                    int t = tid + i * 256;
                    int e = t >> 3, sg = t & 7;
                    cp16(sb + G3_W1 + (e * SWN + sg * 8) * 2,
                         w1 + (size_t)e * HID_ + jn + sg * 8);
                }
                CP_COMMIT();
            }

            const int n2 = wn * 64;
            #pragma unroll
            for (int kf = 0; kf < 4; ++kf) {
                const int k0 = kf * 16;
                uint32_t af[2][4], bq[4][4];
                #pragma unroll
                for (int mi = 0; mi < 2; ++mi) {
                    uint32_t ro = (uint32_t)((m0 + mi * 16 + lrow) * SWN + k0 + lcol) * 2;
                    ldsm4(af[mi], sb + G3_AC + ro);
                }
                #pragma unroll
                for (int nj = 0; nj < 4; ++nj) {
                    uint32_t ro = (uint32_t)((k0 + lrow) * SW2 + n2 + nj * 16 + lcol) * 2;
                    ldsm4t(bq[nj], sb + G3_W2(buf) + ro);
                }
                #pragma unroll
                for (int mi = 0; mi < 2; ++mi)
                    #pragma unroll
                    for (int nj = 0; nj < 4; ++nj)
                        #pragma unroll
                        for (int hh = 0; hh < 2; ++hh)
                            mma16816h(acc2[mi][nj * 2 + hh], af[mi], &bq[nj][hh * 2]);
            }
            __syncthreads();
        }

        {
            const int n2 = wn * 64;
            float* base = partial + ((size_t)(2 * cta + seg) << 14);
            #pragma unroll
            for (int mi = 0; mi < 2; ++mi) {
                const int row = m0 + mi * 16 + gid;
                #pragma unroll
                for (int nf = 0; nf < 8; ++nf) {
                    const int col = n2 + nf * 8 + tig * 2;
                    *(float2*)(base + row * E_ + col) =
                        make_float2(acc2[mi][nf][0], acc2[mi][nf][1]);
                    *(float2*)(base + (row + 8) * E_ + col) =
                        make_float2(acc2[mi][nf][2], acc2[mi][nf][3]);
                }
            }
        }
        seg++;
    }
}

// ---------------------------------------------------------------------------
// Final: out = x2 + bf2 + sum of covering partial slots
// ---------------------------------------------------------------------------
__global__ void k_final3(const float* __restrict__ x2, const float* __restrict__ partial,
                         const float* __restrict__ bf2, float* __restrict__ out) {
    int idx = blockIdx.x * blockDim.x + threadIdx.x;
    if (idx >= NTOK * E_) return;
    int e = idx & 127;
    int tok = idx >> 7;
    int t = tok >> 7;
    int row = tok & 127;

    int c_lo = (int)((((long long)t * 1024 + 1) * FFN_GRID - 1) >> 15);
    int c_hi = (int)((((long long)(t + 1) * 1024) * FFN_GRID - 1) >> 15);

    float s = x2[idx] + bf2[e];
    for (int c = c_lo; c <= c_hi; ++c) {
        int u0c = (int)(((long long)c << 15) / FFN_GRID);
        int seg = ((u0c >> 10) == t) ? 0 : 1;
        s += partial[((size_t)(2 * c + seg) << 14) + (row << 7) + e];
    }
    out[idx] = s;
}

// ---------------------------------------------------------------------------
// Launch
// ---------------------------------------------------------------------------
extern "C" void kernel_launch(void* const* d_in, const int* in_sizes, int n_in,
                              void* d_out, int out_size) {
    const float* x   = (const float*)d_in[0];
    const float* Wk  = (const float*)d_in[1];
    const float* Wq  = (const float*)d_in[2];
    const float* Wv  = (const float*)d_in[3];
    const float* Wo  = (const float*)d_in[4];
    const float* bo  = (const float*)d_in[5];
    const float* g1  = (const float*)d_in[6];
    const float* be1 = (const float*)d_in[7];
    const float* g2  = (const float*)d_in[8];
    const float* be2 = (const float*)d_in[9];
    const float* W1  = (const float*)d_in[10];
    const float* bf1 = (const float*)d_in[11];
    const float* W2  = (const float*)d_in[12];
    const float* bf2 = (const float*)d_in[13];
    float* out = (float*)d_out;

    float *pq, *pk, *pv, *px2, *ppart;
    __half *ph1f, *paof, *ph2f, *pw1f, *pw2f, *pwqf, *pwof;
    cudaGetSymbolAddress((void**)&pq,    g_q);
    cudaGetSymbolAddress((void**)&pk,    g_k);
    cudaGetSymbolAddress((void**)&pv,    g_v);
    cudaGetSymbolAddress((void**)&px2,   g_x2);
    cudaGetSymbolAddress((void**)&ppart, g_part2);
    cudaGetSymbolAddress((void**)&ph1f,  g_h1f);
    cudaGetSymbolAddress((void**)&paof,  g_aof);
    cudaGetSymbolAddress((void**)&ph2f,  g_h2f);
    cudaGetSymbolAddress((void**)&pw1f,  g_w1f);
    cudaGetSymbolAddress((void**)&pw2f,  g_w2f);
    cudaGetSymbolAddress((void**)&pwqf,  g_wqkvf);
    cudaGetSymbolAddress((void**)&pwof,  g_wof);

    cudaFuncSetAttribute(k_ffn4, cudaFuncAttributeMaxDynamicSharedMemorySize, FFN_SMEM4);
    cudaFuncSetAttribute(k_qkv_h, cudaFuncAttributeMaxDynamicSharedMemorySize, QKV_SMEM_H);
    cudaFuncSetAttribute(k_oproj_h, cudaFuncAttributeMaxDynamicSharedMemorySize, OP_SMEM_H);
    cudaFuncSetAttribute(k_attn3, cudaFuncAttributeMaxDynamicSharedMemorySize, AT_SMEM);

    const int nW = E_ * HID_ / 4;
    k_cvthalf<<<(nW + 255) / 256, 256>>>(W1, pw1f, nW);
    k_cvthalf<<<(nW + 255) / 256, 256>>>(W2, pw2f, nW);
    k_cvthalf<<<(E_ * E_ / 4 + 255) / 256, 256>>>(Wo, pwof, E_ * E_ / 4);
    k_prep_wqkv_h<<<(E_ * 384 + 255) / 256, 256>>>(Wq, Wk, Wv, pwqf);

    k_ln_half<<<NTOK / 4, 128>>>(x, g1, be1, ph1f);
    k_qkv_h<<<dim3(NTOK / 64, 3), 256, QKV_SMEM_H>>>(ph1f, pwqf, pq, pk, pv);
    k_attn3<<<dim3(16, 16), 256, AT_SMEM>>>(pq, pk, pv, paof);
    k_oproj_h<<<NTOK / 64, 256, OP_SMEM_H>>>(paof, pwof, bo, x, g2, be2, px2, ph2f);
    k_ffn4<<<FFN_GRID, 256, FFN_SMEM4>>>(ph2f, pw1f, pw2f, bf1, ppart);
    k_final3<<<(NTOK * E_ + 255) / 256, 256>>>(px2, ppart, bf2, out);
}

// round 15
// speedup vs baseline: 1.0721x; 1.0721x over previous
#include <cuda_runtime.h>
#include <cuda_bf16.h>
#include <cuda_fp16.h>
#include <cstdint>
#include <math.h>

// ---------------------------------------------------------------------------
// Problem constants
// ---------------------------------------------------------------------------
#define B_  2
#define T_  2048
#define E_  128
#define H_  8
#define HS_ 16
#define HID_ 65536
#define NTOK (B_ * T_)          // 4096
#define EPS_ 1e-5f
#define ATT_SCALE 0.08838834764831845f   // 1/sqrt(128)

// FFN tiling (1-pass fp16, JC=64, 256 threads, 2 CTAs/SM)  [R13 winner, frozen]
#define FFN_M 128
#define JC2 64
#define NCHUNK2 (HID_ / JC2)        // 1024
#define NTILE (NTOK / FFN_M)        // 32
#define TOT2 (NTILE * NCHUNK2)      // 32768
#define FFN_GRID 888

#define SH   136
#define SWN  72
#define SW2  136

#define G3_H 0
#define G3_W1 34816
#define G3_W2(b) (53248 + (b) * 17408)
#define G3_AC 88064
#define FFN_SMEM4 106496

// QKV / OPROJ fp16 1-pass smem
#define GH_A 0                     // 64 x SH x 2 = 17408
#define GH_W 17408                 // 128 x SH x 2 = 34816
#define QKV_SMEM_H 52224
#define OP_X2T_H 52224             // 64 x 132 x 4 = 33792
#define OP_SMEM_H 86016

// ---------------------------------------------------------------------------
// PTX helpers
// ---------------------------------------------------------------------------
__device__ __forceinline__ uint32_t smem_u32(const void* p) {
    uint32_t a;
    asm("{ .reg .u64 t; cvta.to.shared.u64 t, %1; cvt.u32.u64 %0, t; }"
        : "=r"(a) : "l"(p));
    return a;
}
__device__ __forceinline__ void ldsm4(uint32_t a[4], uint32_t addr) {
    asm volatile("ldmatrix.sync.aligned.m8n8.x4.shared.b16 {%0,%1,%2,%3}, [%4];"
                 : "=r"(a[0]), "=r"(a[1]), "=r"(a[2]), "=r"(a[3]) : "r"(addr));
}
__device__ __forceinline__ void ldsm4t(uint32_t a[4], uint32_t addr) {
    asm volatile("ldmatrix.sync.aligned.m8n8.x4.trans.shared.b16 {%0,%1,%2,%3}, [%4];"
                 : "=r"(a[0]), "=r"(a[1]), "=r"(a[2]), "=r"(a[3]) : "r"(addr));
}
__device__ __forceinline__ void mma16816h(float c[4], const uint32_t a[4],
                                          const uint32_t b[2]) {
    asm volatile("mma.sync.aligned.m16n8k16.row.col.f32.f16.f16.f32 "
                 "{%0,%1,%2,%3}, {%4,%5,%6,%7}, {%8,%9}, {%0,%1,%2,%3};"
                 : "+f"(c[0]), "+f"(c[1]), "+f"(c[2]), "+f"(c[3])
                 : "r"(a[0]), "r"(a[1]), "r"(a[2]), "r"(a[3]),
                   "r"(b[0]), "r"(b[1]));
}
__device__ __forceinline__ void cp16(uint32_t s, const void* g) {
    asm volatile("cp.async.cg.shared.global [%0], [%1], 16;" :: "r"(s), "l"(g));
}
#define CP_COMMIT() asm volatile("cp.async.commit_group;" ::: "memory")
#define CP_WAIT1()  asm volatile("cp.async.wait_group 1;" ::: "memory")
#define CP_WAIT0()  asm volatile("cp.async.wait_group 0;" ::: "memory")

__device__ __forceinline__ uint32_t pack_f16(float a, float b) {
    __half2 h = __floats2half2_rn(a, b);
    return *reinterpret_cast<uint32_t*>(&h);
}

// ---------------------------------------------------------------------------
// Scratch
// ---------------------------------------------------------------------------
__device__ float g_q  [B_ * H_ * T_ * HS_];
__device__ float g_k  [B_ * H_ * T_ * HS_];
__device__ float g_v  [B_ * H_ * T_ * HS_];
__device__ float g_x2 [NTOK * E_];
__device__ float g_part2[2 * FFN_GRID * FFN_M * E_];
__device__ __half g_h1f [NTOK * E_];
__device__ __half g_aof [NTOK * E_];
__device__ __half g_h2f [NTOK * E_];
__device__ __half g_w1f [E_ * HID_];
__device__ __half g_w2f [HID_ * E_];
__device__ __half g_wqkvf[E_ * 384];
__device__ __half g_wof [E_ * E_];

// ---------------------------------------------------------------------------
// fp32 -> fp16 convert
// ---------------------------------------------------------------------------
__global__ void k_cvthalf(const float* __restrict__ src,
                          __half* __restrict__ dst, int n4) {
    int i = blockIdx.x * 256 + threadIdx.x;
    if (i >= n4) return;
    float4 v = ((const float4*)src)[i];
    uint2 o;
    o.x = pack_f16(v.x, v.y);
    o.y = pack_f16(v.z, v.w);
    ((uint2*)dst)[i] = o;
}

// Build Wqkv [E][384] fp16 from Wq/Wk/Wv [H][E][HS]
__global__ void k_prep_wqkv_h(const float* __restrict__ Wq, const float* __restrict__ Wk,
                              const float* __restrict__ Wv, __half* __restrict__ o) {
    int idx = blockIdx.x * 256 + threadIdx.x;
    if (idx >= E_ * 384) return;
    int e = idx / 384, n = idx % 384;
    int which = n >> 7, r = n & 127, h = r >> 4, hd = r & 15;
    const float* W = (which == 0) ? Wq : (which == 1) ? Wk : Wv;
    o[idx] = __float2half_rn(W[((size_t)h * E_ + e) * HS_ + hd]);
}

// ---------------------------------------------------------------------------
// LayerNorm with fp16 output (LN1)
// ---------------------------------------------------------------------------
__global__ void k_ln_half(const float* __restrict__ x, const float* __restrict__ g,
                          const float* __restrict__ b, __half* __restrict__ of) {
    int t = blockIdx.x * 4 + (threadIdx.x >> 5);
    int lane = threadIdx.x & 31;
    float4 a = ((const float4*)(x + (size_t)t * E_))[lane];

    float s = a.x + a.y + a.z + a.w;
    #pragma unroll
    for (int o = 16; o; o >>= 1) s += __shfl_xor_sync(0xffffffffu, s, o);
    float mu = s * (1.0f / E_);

    float dx = a.x - mu, dy = a.y - mu, dz = a.z - mu, dw = a.w - mu;
    float v = dx*dx + dy*dy + dz*dz + dw*dw;
    #pragma unroll
    for (int o = 16; o; o >>= 1) v += __shfl_xor_sync(0xffffffffu, v, o);
    float rs = rsqrtf(v * (1.0f / E_) + EPS_);

    float4 gg = ((const float4*)g)[lane];
    float4 bb = ((const float4*)b)[lane];
    uint2 hp;
    hp.x = pack_f16(dx * rs * gg.x + bb.x, dy * rs * gg.y + bb.y);
    hp.y = pack_f16(dz * rs * gg.z + bb.z, dw * rs * gg.w + bb.w);
    ((uint2*)(of + (size_t)t * E_))[lane] = hp;
}

// ---------------------------------------------------------------------------
// QKV via fp16 1-pass mma: grid (NTOK/64, 3 slabs), 256 thr
// ---------------------------------------------------------------------------
__global__ void __launch_bounds__(256, 1)
k_qkv_h(const __half* __restrict__ af, const __half* __restrict__ wf,
        float* __restrict__ q, float* __restrict__ k, float* __restrict__ v) {
    extern __shared__ char smem[];
    const uint32_t sb = smem_u32(smem);
    const int tid = threadIdx.x, wid = tid >> 5, lane = tid & 31;
    const int gid = lane >> 2, tig = lane & 3;
    const int lrow = (lane & 7) + ((lane >> 3) & 1) * 8;
    const int lcol = ((lane >> 4) & 1) * 8;
    const int wm = wid & 1, wn = wid >> 1;
    const int tok0 = blockIdx.x * 64;
    const int slab = blockIdx.y;
    const int m0 = wm * 32, n0 = wn * 32;

    for (int i = tid; i < 1024; i += 256) {
        int r = i >> 4, s = i & 15;
        *(float4*)(smem + GH_A + (r * SH + s * 8) * 2) =
            *(const float4*)(af + (size_t)(tok0 + r) * E_ + s * 8);
    }
    for (int i = tid; i < 2048; i += 256) {
        int r = i >> 4, s = i & 15;
        *(float4*)(smem + GH_W + (r * SH + s * 8) * 2) =
            *(const float4*)(wf + (size_t)r * 384 + slab * 128 + s * 8);
    }
    __syncthreads();

    float acc[2][4][4];
    #pragma unroll
    for (int a = 0; a < 2; ++a)
        #pragma unroll
        for (int b = 0; b < 4; ++b)
            #pragma unroll
            for (int c = 0; c < 4; ++c) acc[a][b][c] = 0.f;

    #pragma unroll
    for (int kf = 0; kf < 8; ++kf) {
        const int k0 = kf * 16;
        uint32_t afr[2][4], bq[2][4];
        #pragma unroll
        for (int mi = 0; mi < 2; ++mi) {
            uint32_t ro = (uint32_t)((m0 + mi * 16 + lrow) * SH + k0 + lcol) * 2;
            ldsm4(afr[mi], sb + GH_A + ro);
        }
        #pragma unroll
        for (int g = 0; g < 2; ++g) {
            uint32_t ro = (uint32_t)((k0 + lrow) * SH + n0 + g * 16 + lcol) * 2;
            ldsm4t(bq[g], sb + GH_W + ro);
        }
        #pragma unroll
        for (int mi = 0; mi < 2; ++mi)
            #pragma unroll
            for (int g = 0; g < 2; ++g)
                #pragma unroll
                for (int hh = 0; hh < 2; ++hh)
                    mma16816h(acc[mi][g * 2 + hh], afr[mi], &bq[g][hh * 2]);
    }

    float* dst = (slab == 0) ? q : (slab == 1) ? k : v;
    #pragma unroll
    for (int mi = 0; mi < 2; ++mi) {
        int tg = tok0 + m0 + mi * 16 + gid;
        int b = tg >> 11, tl = tg & 2047;
        #pragma unroll
        for (int ni = 0; ni < 4; ++ni) {
            int n = n0 + ni * 8 + tig * 2;
            int h = n >> 4, hd = n & 15;
            float* p = dst + (((size_t)(b * 8 + h)) * T_ + tl) * HS_ + hd;
            *(float2*)p = make_float2(acc[mi][ni][0], acc[mi][ni][1]);
            *(float2*)(p + 8 * HS_) = make_float2(acc[mi][ni][2], acc[mi][ni][3]);
        }
    }
}

// ---------------------------------------------------------------------------
// Attention (R13 winner structure; fp16 single output)
// grid (8, 16), 256 thr; complementary block pairing for causal balance.
// ---------------------------------------------------------------------------
__global__ void __launch_bounds__(256, 1)
k_attn2h(const float* __restrict__ q, const float* __restrict__ k,
         const float* __restrict__ v, __half* __restrict__ aof) {
    __shared__ float Ks[2][128][16];
    __shared__ float Vs[2][128][16];
    const int tid = threadIdx.x, wid = tid >> 5, lane = tid & 31;
    const int bh = blockIdx.y, qb = blockIdx.x;
    const int wg = wid >> 2;
    const int qblk = wg ? (15 - qb) : qb;
    const int t = qblk * 128 + (wid & 3) * 32 + lane;
    const int mytiles = qblk + 1;
    const int ntiles = 16 - qb;

    const float* qp = q + ((size_t)bh * T_ + t) * HS_;
    float4 q0 = ((const float4*)qp)[0];
    float4 q1 = ((const float4*)qp)[1];
    float4 q2 = ((const float4*)qp)[2];
    float4 q3 = ((const float4*)qp)[3];
    const float* kb_ = k + (size_t)bh * T_ * HS_;
    const float* vb_ = v + (size_t)bh * T_ * HS_;
    const uint32_t ksa = smem_u32(Ks), vsa = smem_u32(Vs);

    float m = -1e30f, l = 0.f;
    float o[16];
    #pragma unroll
    for (int d = 0; d < 16; ++d) o[d] = 0.f;

    #pragma unroll
    for (int i = 0; i < 2; ++i) {
        int f = tid + i * 256;
        int row = f >> 2, sg = f & 3;
        cp16(ksa + row * 64 + sg * 16, kb_ + (size_t)row * HS_ + sg * 4);
        cp16(vsa + row * 64 + sg * 16, vb_ + (size_t)row * HS_ + sg * 4);
    }
    CP_COMMIT();

    for (int it = 0; it < ntiles; ++it) {
        const int buf = it & 1;
        if (it + 1 < ntiles) {
            int kb2 = (it + 1) * 128;
            int ob = (buf ^ 1) * 8192;
            #pragma unroll
            for (int i = 0; i < 2; ++i) {
                int f = tid + i * 256;
                int row = f >> 2, sg = f & 3;
                cp16(ksa + ob + row * 64 + sg * 16, kb_ + (size_t)(kb2 + row) * HS_ + sg * 4);
                cp16(vsa + ob + row * 64 + sg * 16, vb_ + (size_t)(kb2 + row) * HS_ + sg * 4);
            }
        }
        CP_COMMIT();
        CP_WAIT1();
        __syncthreads();

        if (it < mytiles) {
            const int kbase = it * 128;
            #pragma unroll 2
            for (int j = 0; j < 128; ++j) {
                const float4* kr = (const float4*)&Ks[buf][j][0];
                float4 k0 = kr[0], k1 = kr[1], k2 = kr[2], k3 = kr[3];
                float sc = q0.x*k0.x + q0.y*k0.y + q0.z*k0.z + q0.w*k0.w
                         + q1.x*k1.x + q1.y*k1.y + q1.z*k1.z + q1.w*k1.w
                         + q2.x*k2.x + q2.y*k2.y + q2.z*k2.z + q2.w*k2.w
                         + q3.x*k3.x + q3.y*k3.y + q3.z*k3.z + q3.w*k3.w;
                sc *= ATT_SCALE;
                if (kbase + j > t) sc = -1e30f;
                float mn = fmaxf(m, sc);
                float scale = __expf(m - mn);
                float w = __expf(sc - mn);
                l = l * scale + w;
                const float4* vr = (const float4*)&Vs[buf][j][0];
                float4 v0 = vr[0], v1 = vr[1], v2 = vr[2], v3 = vr[3];
                o[0]  = o[0]*scale  + w*v0.x;  o[1]  = o[1]*scale  + w*v0.y;
                o[2]  = o[2]*scale  + w*v0.z;  o[3]  = o[3]*scale  + w*v0.w;
                o[4]  = o[4]*scale  + w*v1.x;  o[5]  = o[5]*scale  + w*v1.y;
                o[6]  = o[6]*scale  + w*v1.z;  o[7]  = o[7]*scale  + w*v1.w;
                o[8]  = o[8]*scale  + w*v2.x;  o[9]  = o[9]*scale  + w*v2.y;
                o[10] = o[10]*scale + w*v2.z;  o[11] = o[11]*scale + w*v2.w;
                o[12] = o[12]*scale + w*v3.x;  o[13] = o[13]*scale + w*v3.y;
                o[14] = o[14]*scale + w*v3.z;  o[15] = o[15]*scale + w*v3.w;
                m = mn;
            }
        }
        __syncthreads();
    }

    // write fp16 output
    float inv = 1.0f / l;
    int b = bh >> 3, h = bh & 7;
    size_t base = ((size_t)b * T_ + t) * E_ + h * HS_;
    uint32_t hp[8];
    #pragma unroll
    for (int d = 0; d < 8; ++d)
        hp[d] = pack_f16(o[2 * d] * inv, o[2 * d + 1] * inv);
    ((uint4*)(aof + base))[0] = make_uint4(hp[0], hp[1], hp[2], hp[3]);
    ((uint4*)(aof + base))[1] = make_uint4(hp[4], hp[5], hp[6], hp[7]);
}

// ---------------------------------------------------------------------------
// O-proj fp16 1-pass + residual + fused LN2 (h2 fp16 out)
// ---------------------------------------------------------------------------
__global__ void __launch_bounds__(256, 1)
k_oproj_h(const __half* __restrict__ af, const __half* __restrict__ wf,
          const float* __restrict__ bo, const float* __restrict__ x,
          const float* __restrict__ g2, const float* __restrict__ be2,
          float* __restrict__ x2, __half* __restrict__ h2f) {
    extern __shared__ char smem[];
    const uint32_t sb = smem_u32(smem);
    float* x2t = (float*)(smem + OP_X2T_H);
    const int tid = threadIdx.x, wid = tid >> 5, lane = tid & 31;
    const int gid = lane >> 2, tig = lane & 3;
    const int lrow = (lane & 7) + ((lane >> 3) & 1) * 8;
    const int lcol = ((lane >> 4) & 1) * 8;
    const int wm = wid & 1, wn = wid >> 1;
    const int tok0 = blockIdx.x * 64;
    const int m0 = wm * 32, n0 = wn * 32;

    for (int i = tid; i < 1024; i += 256) {
        int r = i >> 4, s = i & 15;
        *(float4*)(smem + GH_A + (r * SH + s * 8) * 2) =
            *(const float4*)(af + (size_t)(tok0 + r) * E_ + s * 8);
    }
    for (int i = tid; i < 2048; i += 256) {
        int r = i >> 4, s = i & 15;
        *(float4*)(smem + GH_W + (r * SH + s * 8) * 2) =
            *(const float4*)(wf + (size_t)r * E_ + s * 8);
    }
    __syncthreads();

    float acc[2][4][4];
    #pragma unroll
    for (int a = 0; a < 2; ++a)
        #pragma unroll
        for (int b = 0; b < 4; ++b)
            #pragma unroll
            for (int c = 0; c < 4; ++c) acc[a][b][c] = 0.f;

    #pragma unroll
    for (int kf = 0; kf < 8; ++kf) {
        const int k0 = kf * 16;
        uint32_t afr[2][4], bq[2][4];
        #pragma unroll
        for (int mi = 0; mi < 2; ++mi) {
            uint32_t ro = (uint32_t)((m0 + mi * 16 + lrow) * SH + k0 + lcol) * 2;
            ldsm4(afr[mi], sb + GH_A + ro);
        }
        #pragma unroll
        for (int g = 0; g < 2; ++g) {
            uint32_t ro = (uint32_t)((k0 + lrow) * SH + n0 + g * 16 + lcol) * 2;
            ldsm4t(bq[g], sb + GH_W + ro);
        }
        #pragma unroll
        for (int mi = 0; mi < 2; ++mi)
            #pragma unroll
            for (int g = 0; g < 2; ++g)
                #pragma unroll
                for (int hh = 0; hh < 2; ++hh)
                    mma16816h(acc[mi][g * 2 + hh], afr[mi], &bq[g][hh * 2]);
    }

    #pragma unroll
    for (int mi = 0; mi < 2; ++mi) {
        int rl = m0 + mi * 16 + gid;
        #pragma unroll
        for (int ni = 0; ni < 4; ++ni) {
            int col = n0 + ni * 8 + tig * 2;
            float2 bia = *(const float2*)(bo + col);
            float2 xr0 = *(const float2*)(x + (size_t)(tok0 + rl) * E_ + col);
            float2 xr1 = *(const float2*)(x + (size_t)(tok0 + rl + 8) * E_ + col);
            x2t[rl * 132 + col]           = acc[mi][ni][0] + bia.x + xr0.x;
            x2t[rl * 132 + col + 1]       = acc[mi][ni][1] + bia.y + xr0.y;
            x2t[(rl + 8) * 132 + col]     = acc[mi][ni][2] + bia.x + xr1.x;
            x2t[(rl + 8) * 132 + col + 1] = acc[mi][ni][3] + bia.y + xr1.y;
        }
    }
    __syncthreads();

    float4 gg = ((const float4*)g2)[lane];
    float4 bb = ((const float4*)be2)[lane];
    #pragma unroll
    for (int r = 0; r < 8; ++r) {
        int tokl = wid * 8 + r;
        float4 a = *(float4*)(x2t + tokl * 132 + lane * 4);
        float s = a.x + a.y + a.z + a.w;
        #pragma unroll
        for (int o = 16; o; o >>= 1) s += __shfl_xor_sync(0xffffffffu, s, o);
        float mu = s * (1.0f / E_);
        float dx = a.x - mu, dy = a.y - mu, dz = a.z - mu, dw = a.w - mu;
        float vv = dx*dx + dy*dy + dz*dz + dw*dw;
        #pragma unroll
        for (int o = 16; o; o >>= 1) vv += __shfl_xor_sync(0xffffffffu, vv, o);
        float rs = rsqrtf(vv * (1.0f / E_) + EPS_);

        ((float4*)(x2 + (size_t)(tok0 + tokl) * E_))[lane] = a;

        uint2 hp;
        hp.x = pack_f16(dx * rs * gg.x + bb.x, dy * rs * gg.y + bb.y);
        hp.y = pack_f16(dz * rs * gg.z + bb.z, dw * rs * gg.w + bb.w);
        ((uint2*)(h2f + (size_t)(tok0 + tokl) * E_))[lane] = hp;
    }
}

// ---------------------------------------------------------------------------
// FFN (R13 winner, frozen): fp16 1-pass, JC=64, 256 thr, 2 CTAs/SM
// ---------------------------------------------------------------------------
__global__ void __launch_bounds__(256, 2)
k_ffn4(const __half* __restrict__ h2,
       const __half* __restrict__ w1, const __half* __restrict__ w2,
       const float* __restrict__ bf1, float* __restrict__ partial) {
    extern __shared__ char smem[];
    const uint32_t sb = smem_u32(smem);
    const int tid = threadIdx.x, wid = tid >> 5, lane = tid & 31;
    const int gid = lane >> 2, tig = lane & 3;
    const int lrow = (lane & 7) + ((lane >> 3) & 1) * 8;
    const int lcol = ((lane >> 4) & 1) * 8;
    const int wm = wid & 3, wn = wid >> 2;
    const int m0 = wm * 32;
    const int cta = blockIdx.x;
    const int u0 = (int)(((long long)cta * TOT2) / FFN_GRID);
    const int u1 = (int)(((long long)(cta + 1) * TOT2) / FFN_GRID);

    {
        int jb = (u0 & (NCHUNK2 - 1)) * JC2;
        #pragma unroll
        for (int i = 0; i < 4; ++i) {
            int t = tid + i * 256;
            int e = t >> 3, sg = t & 7;
            cp16(sb + G3_W1 + (e * SWN + sg * 8) * 2, w1 + (size_t)e * HID_ + jb + sg * 8);
            int j = t >> 4, sg2 = t & 15;
            cp16(sb + G3_W2(0) + (j * SW2 + sg2 * 8) * 2, w2 + (size_t)(jb + j) * E_ + sg2 * 8);
        }
    }
    CP_COMMIT();

    int u = u0, seg = 0;
    while (u < u1) {
        const int tile = u >> 10;
        const int useg_end = min(u1, (tile + 1) << 10);
        const int tok0 = tile * FFN_M;

        for (int i = tid; i < 2048; i += 256) {
            int r = i >> 4, s = i & 15;
            *(float4*)(smem + G3_H + (r * SH + s * 8) * 2) =
                *(const float4*)(h2 + (size_t)(tok0 + r) * E_ + s * 8);
        }
        float acc2[2][8][4];
        #pragma unroll
        for (int a = 0; a < 2; ++a)
            #pragma unroll
            for (int b = 0; b < 8; ++b)
                #pragma unroll
                for (int c = 0; c < 4; ++c) acc2[a][b][c] = 0.f;
        __syncthreads();

        for (; u < useg_end; ++u) {
            const int buf = (u - u0) & 1;
            const int jb = (u & (NCHUNK2 - 1)) * JC2;
            const bool more = (u + 1 < u1);

            if (more) {
                int jn = ((u + 1) & (NCHUNK2 - 1)) * JC2;
                #pragma unroll
                for (int i = 0; i < 4; ++i) {
                    int t = tid + i * 256;
                    int j = t >> 4, sg2 = t & 15;
                    cp16(sb + G3_W2(buf ^ 1) + (j * SW2 + sg2 * 8) * 2,
                         w2 + (size_t)(jn + j) * E_ + sg2 * 8);
                }
                CP_COMMIT();
                CP_WAIT1();
            } else {
                CP_WAIT0();
            }
            __syncthreads();

            const int n1 = wn * 32;
            float acc1[2][4][4];
            #pragma unroll
            for (int a = 0; a < 2; ++a)
                #pragma unroll
                for (int b = 0; b < 4; ++b)
                    #pragma unroll
                    for (int d = 0; d < 4; ++d) acc1[a][b][d] = 0.f;

            #pragma unroll
            for (int kf = 0; kf < 8; ++kf) {
                const int k0 = kf * 16;
                uint32_t af[2][4], bq[2][4];
                #pragma unroll
                for (int mi = 0; mi < 2; ++mi) {
                    uint32_t ro = (uint32_t)((m0 + mi * 16 + lrow) * SH + k0 + lcol) * 2;
                    ldsm4(af[mi], sb + G3_H + ro);
                }
                #pragma unroll
                for (int g = 0; g < 2; ++g) {
                    uint32_t ro = (uint32_t)((k0 + lrow) * SWN + n1 + g * 16 + lcol) * 2;
                    ldsm4t(bq[g], sb + G3_W1 + ro);
                }
                #pragma unroll
                for (int mi = 0; mi < 2; ++mi)
                    #pragma unroll
                    for (int g = 0; g < 2; ++g)
                        #pragma unroll
                        for (int hh = 0; hh < 2; ++hh)
                            mma16816h(acc1[mi][g * 2 + hh], af[mi], &bq[g][hh * 2]);
            }

            #pragma unroll
            for (int ni = 0; ni < 4; ++ni) {
                const int col = n1 + ni * 8 + tig * 2;
                const float2 bia = *(const float2*)(bf1 + jb + col);
                #pragma unroll
                for (int mi = 0; mi < 2; ++mi) {
                    const int row = m0 + mi * 16 + gid;
                    float a0 = fmaxf(acc1[mi][ni][0] + bia.x, 0.f);
                    float a1 = fmaxf(acc1[mi][ni][1] + bia.y, 0.f);
                    float a2 = fmaxf(acc1[mi][ni][2] + bia.x, 0.f);
                    float a3 = fmaxf(acc1[mi][ni][3] + bia.y, 0.f);
                    *(uint32_t*)(smem + G3_AC + (uint32_t)(row * SWN + col) * 2) =
                        pack_f16(a0, a1);
                    *(uint32_t*)(smem + G3_AC + (uint32_t)((row + 8) * SWN + col) * 2) =
                        pack_f16(a2, a3);
                }
            }
            __syncthreads();

            if (more) {
                int jn = ((u + 1) & (NCHUNK2 - 1)) * JC2;
                #pragma unroll
                for (int i = 0; i < 4; ++i) {
                    int t = tid + i * 256;
                    int e = t >> 3, sg = t & 7;
                    cp16(sb + G3_W1 + (e * SWN + sg * 8) * 2,
                         w1 + (size_t)e * HID_ + jn + sg * 8);
                }
                CP_COMMIT();
            }

            const int n2 = wn * 64;
            #pragma unroll
            for (int kf = 0; kf < 4; ++kf) {
                const int k0 = kf * 16;
                uint32_t af[2][4], bq[4][4];
                #pragma unroll
                for (int mi = 0; mi < 2; ++mi) {
                    uint32_t ro = (uint32_t)((m0 + mi * 16 + lrow) * SWN + k0 + lcol) * 2;
                    ldsm4(af[mi], sb + G3_AC + ro);
                }
                #pragma unroll
                for (int nj = 0; nj < 4; ++nj) {
                    uint32_t ro = (uint32_t)((k0 + lrow) * SW2 + n2 + nj * 16 + lcol) * 2;
                    ldsm4t(bq[nj], sb + G3_W2(buf) + ro);
                }
                #pragma unroll
                for (int mi = 0; mi < 2; ++mi)
                    #pragma unroll
                    for (int nj = 0; nj < 4; ++nj)
                        #pragma unroll
                        for (int hh = 0; hh < 2; ++hh)
                            mma16816h(acc2[mi][nj * 2 + hh], af[mi], &bq[nj][hh * 2]);
            }
            __syncthreads();
        }

        {
            const int n2 = wn * 64;
            float* base = partial + ((size_t)(2 * cta + seg) << 14);
            #pragma unroll
            for (int mi = 0; mi < 2; ++mi) {
                const int row = m0 + mi * 16 + gid;
                #pragma unroll
                for (int nf = 0; nf < 8; ++nf) {
                    const int col = n2 + nf * 8 + tig * 2;
                    *(float2*)(base + row * E_ + col) =
                        make_float2(acc2[mi][nf][0], acc2[mi][nf][1]);
                    *(float2*)(base + (row + 8) * E_ + col) =
                        make_float2(acc2[mi][nf][2], acc2[mi][nf][3]);
                }
            }
        }
        seg++;
    }
}

// ---------------------------------------------------------------------------
// Final: out = x2 + bf2 + sum of covering partial slots
// ---------------------------------------------------------------------------
__global__ void k_final3(const float* __restrict__ x2, const float* __restrict__ partial,
                         const float* __restrict__ bf2, float* __restrict__ out) {
    int idx = blockIdx.x * blockDim.x + threadIdx.x;
    if (idx >= NTOK * E_) return;
    int e = idx & 127;
    int tok = idx >> 7;
    int t = tok >> 7;
    int row = tok & 127;

    int c_lo = (int)((((long long)t * 1024 + 1) * FFN_GRID - 1) >> 15);
    int c_hi = (int)((((long long)(t + 1) * 1024) * FFN_GRID - 1) >> 15);

    float s = x2[idx] + bf2[e];
    for (int c = c_lo; c <= c_hi; ++c) {
        int u0c = (int)(((long long)c << 15) / FFN_GRID);
        int seg = ((u0c >> 10) == t) ? 0 : 1;
        s += partial[((size_t)(2 * c + seg) << 14) + (row << 7) + e];
    }
    out[idx] = s;
}

// ---------------------------------------------------------------------------
// Launch
// ---------------------------------------------------------------------------
extern "C" void kernel_launch(void* const* d_in, const int* in_sizes, int n_in,
                              void* d_out, int out_size) {
    const float* x   = (const float*)d_in[0];
    const float* Wk  = (const float*)d_in[1];
    const float* Wq  = (const float*)d_in[2];
    const float* Wv  = (const float*)d_in[3];
    const float* Wo  = (const float*)d_in[4];
    const float* bo  = (const float*)d_in[5];
    const float* g1  = (const float*)d_in[6];
    const float* be1 = (const float*)d_in[7];
    const float* g2  = (const float*)d_in[8];
    const float* be2 = (const float*)d_in[9];
    const float* W1  = (const float*)d_in[10];
    const float* bf1 = (const float*)d_in[11];
    const float* W2  = (const float*)d_in[12];
    const float* bf2 = (const float*)d_in[13];
    float* out = (float*)d_out;

    float *pq, *pk, *pv, *px2, *ppart;
    __half *ph1f, *paof, *ph2f, *pw1f, *pw2f, *pwqf, *pwof;
    cudaGetSymbolAddress((void**)&pq,    g_q);
    cudaGetSymbolAddress((void**)&pk,    g_k);
    cudaGetSymbolAddress((void**)&pv,    g_v);
    cudaGetSymbolAddress((void**)&px2,   g_x2);
    cudaGetSymbolAddress((void**)&ppart, g_part2);
    cudaGetSymbolAddress((void**)&ph1f,  g_h1f);
    cudaGetSymbolAddress((void**)&paof,  g_aof);
    cudaGetSymbolAddress((void**)&ph2f,  g_h2f);
    cudaGetSymbolAddress((void**)&pw1f,  g_w1f);
    cudaGetSymbolAddress((void**)&pw2f,  g_w2f);
    cudaGetSymbolAddress((void**)&pwqf,  g_wqkvf);
    cudaGetSymbolAddress((void**)&pwof,  g_wof);

    cudaFuncSetAttribute(k_ffn4, cudaFuncAttributeMaxDynamicSharedMemorySize, FFN_SMEM4);
    cudaFuncSetAttribute(k_qkv_h, cudaFuncAttributeMaxDynamicSharedMemorySize, QKV_SMEM_H);
    cudaFuncSetAttribute(k_oproj_h, cudaFuncAttributeMaxDynamicSharedMemorySize, OP_SMEM_H);

    const int nW = E_ * HID_ / 4;
    k_cvthalf<<<(nW + 255) / 256, 256>>>(W1, pw1f, nW);
    k_cvthalf<<<(nW + 255) / 256, 256>>>(W2, pw2f, nW);
    k_cvthalf<<<(E_ * E_ / 4 + 255) / 256, 256>>>(Wo, pwof, E_ * E_ / 4);
    k_prep_wqkv_h<<<(E_ * 384 + 255) / 256, 256>>>(Wq, Wk, Wv, pwqf);

    k_ln_half<<<NTOK / 4, 128>>>(x, g1, be1, ph1f);
    k_qkv_h<<<dim3(NTOK / 64, 3), 256, QKV_SMEM_H>>>(ph1f, pwqf, pq, pk, pv);
    k_attn2h<<<dim3(8, 16), 256>>>(pq, pk, pv, paof);
    k_oproj_h<<<NTOK / 64, 256, OP_SMEM_H>>>(paof, pwof, bo, x, g2, be2, px2, ph2f);
    k_ffn4<<<FFN_GRID, 256, FFN_SMEM4>>>(ph2f, pw1f, pw2f, bf1, ppart);
    k_final3<<<(NTOK * E_ + 255) / 256, 256>>>(px2, ppart, bf2, out);
}

// round 16
// speedup vs baseline: 1.0778x; 1.0053x over previous
#include <cuda_runtime.h>
#include <cuda_bf16.h>
#include <cuda_fp16.h>
#include <cstdint>
#include <math.h>

// ---------------------------------------------------------------------------
// Problem constants
// ---------------------------------------------------------------------------
#define B_  2
#define T_  2048
#define E_  128
#define H_  8
#define HS_ 16
#define HID_ 65536
#define NTOK (B_ * T_)          // 4096
#define EPS_ 1e-5f
#define ATT_SCALE 0.08838834764831845f   // 1/sqrt(128)

// FFN tiling (1-pass fp16, JC=64, 256 threads, 2 CTAs/SM)  [R13 winner, frozen]
#define FFN_M 128
#define JC2 64
#define NCHUNK2 (HID_ / JC2)        // 1024
#define NTILE (NTOK / FFN_M)        // 32
#define TOT2 (NTILE * NCHUNK2)      // 32768
#define FFN_GRID 888

#define SH   136
#define SWN  72
#define SW2  136

#define G3_H 0
#define G3_W1 34816
#define G3_W2(b) (53248 + (b) * 17408)
#define G3_AC 88064
#define FFN_SMEM4 106496

// QKV fp16 1-pass smem
#define GH_A 0                     // 64 x SH x 2 = 17408
#define GH_W 17408                 // 128 x SH x 2 = 34816
#define QKV_SMEM_H 52224

// O-proj 32-token tiles
#define OQ_A 0                     // 32 x SH x 2 = 8704
#define OQ_W 8704                  // 128 x SH x 2 = 34816
#define OQ_X2T 43520               // 32 x 132 x 4 = 16896
#define OP_SMEM2 60416

// ---------------------------------------------------------------------------
// PTX helpers
// ---------------------------------------------------------------------------
__device__ __forceinline__ uint32_t smem_u32(const void* p) {
    uint32_t a;
    asm("{ .reg .u64 t; cvta.to.shared.u64 t, %1; cvt.u32.u64 %0, t; }"
        : "=r"(a) : "l"(p));
    return a;
}
__device__ __forceinline__ void ldsm4(uint32_t a[4], uint32_t addr) {
    asm volatile("ldmatrix.sync.aligned.m8n8.x4.shared.b16 {%0,%1,%2,%3}, [%4];"
                 : "=r"(a[0]), "=r"(a[1]), "=r"(a[2]), "=r"(a[3]) : "r"(addr));
}
__device__ __forceinline__ void ldsm4t(uint32_t a[4], uint32_t addr) {
    asm volatile("ldmatrix.sync.aligned.m8n8.x4.trans.shared.b16 {%0,%1,%2,%3}, [%4];"
                 : "=r"(a[0]), "=r"(a[1]), "=r"(a[2]), "=r"(a[3]) : "r"(addr));
}
__device__ __forceinline__ void mma16816h(float c[4], const uint32_t a[4],
                                          const uint32_t b[2]) {
    asm volatile("mma.sync.aligned.m16n8k16.row.col.f32.f16.f16.f32 "
                 "{%0,%1,%2,%3}, {%4,%5,%6,%7}, {%8,%9}, {%0,%1,%2,%3};"
                 : "+f"(c[0]), "+f"(c[1]), "+f"(c[2]), "+f"(c[3])
                 : "r"(a[0]), "r"(a[1]), "r"(a[2]), "r"(a[3]),
                   "r"(b[0]), "r"(b[1]));
}
__device__ __forceinline__ void cp16(uint32_t s, const void* g) {
    asm volatile("cp.async.cg.shared.global [%0], [%1], 16;" :: "r"(s), "l"(g));
}
#define CP_COMMIT() asm volatile("cp.async.commit_group;" ::: "memory")
#define CP_WAIT1()  asm volatile("cp.async.wait_group 1;" ::: "memory")
#define CP_WAIT0()  asm volatile("cp.async.wait_group 0;" ::: "memory")

__device__ __forceinline__ uint32_t pack_f16(float a, float b) {
    __half2 h = __floats2half2_rn(a, b);
    return *reinterpret_cast<uint32_t*>(&h);
}

// ---------------------------------------------------------------------------
// Scratch
// ---------------------------------------------------------------------------
__device__ float g_q  [B_ * H_ * T_ * HS_];
__device__ float g_k  [B_ * H_ * T_ * HS_];
__device__ float g_v  [B_ * H_ * T_ * HS_];
__device__ float g_x2 [NTOK * E_];
__device__ float g_part2[2 * FFN_GRID * FFN_M * E_];
__device__ __half g_h1f [NTOK * E_];
__device__ __half g_aof [NTOK * E_];
__device__ __half g_h2f [NTOK * E_];
__device__ __half g_w1f [E_ * HID_];
__device__ __half g_w2f [HID_ * E_];
__device__ __half g_wqkvf[E_ * 384];
__device__ __half g_wof [E_ * E_];

// ---------------------------------------------------------------------------
// fp32 -> fp16 convert
// ---------------------------------------------------------------------------
__global__ void k_cvthalf(const float* __restrict__ src,
                          __half* __restrict__ dst, int n4) {
    int i = blockIdx.x * 256 + threadIdx.x;
    if (i >= n4) return;
    float4 v = ((const float4*)src)[i];
    uint2 o;
    o.x = pack_f16(v.x, v.y);
    o.y = pack_f16(v.z, v.w);
    ((uint2*)dst)[i] = o;
}

// Build Wqkv [E][384] fp16 from Wq/Wk/Wv [H][E][HS]
__global__ void k_prep_wqkv_h(const float* __restrict__ Wq, const float* __restrict__ Wk,
                              const float* __restrict__ Wv, __half* __restrict__ o) {
    int idx = blockIdx.x * 256 + threadIdx.x;
    if (idx >= E_ * 384) return;
    int e = idx / 384, n = idx % 384;
    int which = n >> 7, r = n & 127, h = r >> 4, hd = r & 15;
    const float* W = (which == 0) ? Wq : (which == 1) ? Wk : Wv;
    o[idx] = __float2half_rn(W[((size_t)h * E_ + e) * HS_ + hd]);
}

// ---------------------------------------------------------------------------
// LayerNorm with fp16 output (LN1)
// ---------------------------------------------------------------------------
__global__ void k_ln_half(const float* __restrict__ x, const float* __restrict__ g,
                          const float* __restrict__ b, __half* __restrict__ of) {
    int t = blockIdx.x * 4 + (threadIdx.x >> 5);
    int lane = threadIdx.x & 31;
    float4 a = ((const float4*)(x + (size_t)t * E_))[lane];

    float s = a.x + a.y + a.z + a.w;
    #pragma unroll
    for (int o = 16; o; o >>= 1) s += __shfl_xor_sync(0xffffffffu, s, o);
    float mu = s * (1.0f / E_);

    float dx = a.x - mu, dy = a.y - mu, dz = a.z - mu, dw = a.w - mu;
    float v = dx*dx + dy*dy + dz*dz + dw*dw;
    #pragma unroll
    for (int o = 16; o; o >>= 1) v += __shfl_xor_sync(0xffffffffu, v, o);
    float rs = rsqrtf(v * (1.0f / E_) + EPS_);

    float4 gg = ((const float4*)g)[lane];
    float4 bb = ((const float4*)b)[lane];
    uint2 hp;
    hp.x = pack_f16(dx * rs * gg.x + bb.x, dy * rs * gg.y + bb.y);
    hp.y = pack_f16(dz * rs * gg.z + bb.z, dw * rs * gg.w + bb.w);
    ((uint2*)(of + (size_t)t * E_))[lane] = hp;
}

// ---------------------------------------------------------------------------
// QKV via fp16 1-pass mma: grid (NTOK/64, 3 slabs), 256 thr
// ---------------------------------------------------------------------------
__global__ void __launch_bounds__(256, 1)
k_qkv_h(const __half* __restrict__ af, const __half* __restrict__ wf,
        float* __restrict__ q, float* __restrict__ k, float* __restrict__ v) {
    extern __shared__ char smem[];
    const uint32_t sb = smem_u32(smem);
    const int tid = threadIdx.x, wid = tid >> 5, lane = tid & 31;
    const int gid = lane >> 2, tig = lane & 3;
    const int lrow = (lane & 7) + ((lane >> 3) & 1) * 8;
    const int lcol = ((lane >> 4) & 1) * 8;
    const int wm = wid & 1, wn = wid >> 1;
    const int tok0 = blockIdx.x * 64;
    const int slab = blockIdx.y;
    const int m0 = wm * 32, n0 = wn * 32;

    for (int i = tid; i < 1024; i += 256) {
        int r = i >> 4, s = i & 15;
        *(float4*)(smem + GH_A + (r * SH + s * 8) * 2) =
            *(const float4*)(af + (size_t)(tok0 + r) * E_ + s * 8);
    }
    for (int i = tid; i < 2048; i += 256) {
        int r = i >> 4, s = i & 15;
        *(float4*)(smem + GH_W + (r * SH + s * 8) * 2) =
            *(const float4*)(wf + (size_t)r * 384 + slab * 128 + s * 8);
    }
    __syncthreads();

    float acc[2][4][4];
    #pragma unroll
    for (int a = 0; a < 2; ++a)
        #pragma unroll
        for (int b = 0; b < 4; ++b)
            #pragma unroll
            for (int c = 0; c < 4; ++c) acc[a][b][c] = 0.f;

    #pragma unroll
    for (int kf = 0; kf < 8; ++kf) {
        const int k0 = kf * 16;
        uint32_t afr[2][4], bq[2][4];
        #pragma unroll
        for (int mi = 0; mi < 2; ++mi) {
            uint32_t ro = (uint32_t)((m0 + mi * 16 + lrow) * SH + k0 + lcol) * 2;
            ldsm4(afr[mi], sb + GH_A + ro);
        }
        #pragma unroll
        for (int g = 0; g < 2; ++g) {
            uint32_t ro = (uint32_t)((k0 + lrow) * SH + n0 + g * 16 + lcol) * 2;
            ldsm4t(bq[g], sb + GH_W + ro);
        }
        #pragma unroll
        for (int mi = 0; mi < 2; ++mi)
            #pragma unroll
            for (int g = 0; g < 2; ++g)
                #pragma unroll
                for (int hh = 0; hh < 2; ++hh)
                    mma16816h(acc[mi][g * 2 + hh], afr[mi], &bq[g][hh * 2]);
    }

    float* dst = (slab == 0) ? q : (slab == 1) ? k : v;
    #pragma unroll
    for (int mi = 0; mi < 2; ++mi) {
        int tg = tok0 + m0 + mi * 16 + gid;
        int b = tg >> 11, tl = tg & 2047;
        #pragma unroll
        for (int ni = 0; ni < 4; ++ni) {
            int n = n0 + ni * 8 + tig * 2;
            int h = n >> 4, hd = n & 15;
            float* p = dst + (((size_t)(b * 8 + h)) * T_ + tl) * HS_ + hd;
            *(float2*)p = make_float2(acc[mi][ni][0], acc[mi][ni][1]);
            *(float2*)(p + 8 * HS_) = make_float2(acc[mi][ni][2], acc[mi][ni][3]);
        }
    }
}

// ---------------------------------------------------------------------------
// Attention (R13 winner structure; fp16 single output) — frozen
// ---------------------------------------------------------------------------
__global__ void __launch_bounds__(256, 1)
k_attn2h(const float* __restrict__ q, const float* __restrict__ k,
         const float* __restrict__ v, __half* __restrict__ aof) {
    __shared__ float Ks[2][128][16];
    __shared__ float Vs[2][128][16];
    const int tid = threadIdx.x, wid = tid >> 5, lane = tid & 31;
    const int bh = blockIdx.y, qb = blockIdx.x;
    const int wg = wid >> 2;
    const int qblk = wg ? (15 - qb) : qb;
    const int t = qblk * 128 + (wid & 3) * 32 + lane;
    const int mytiles = qblk + 1;
    const int ntiles = 16 - qb;

    const float* qp = q + ((size_t)bh * T_ + t) * HS_;
    float4 q0 = ((const float4*)qp)[0];
    float4 q1 = ((const float4*)qp)[1];
    float4 q2 = ((const float4*)qp)[2];
    float4 q3 = ((const float4*)qp)[3];
    const float* kb_ = k + (size_t)bh * T_ * HS_;
    const float* vb_ = v + (size_t)bh * T_ * HS_;
    const uint32_t ksa = smem_u32(Ks), vsa = smem_u32(Vs);

    float m = -1e30f, l = 0.f;
    float o[16];
    #pragma unroll
    for (int d = 0; d < 16; ++d) o[d] = 0.f;

    #pragma unroll
    for (int i = 0; i < 2; ++i) {
        int f = tid + i * 256;
        int row = f >> 2, sg = f & 3;
        cp16(ksa + row * 64 + sg * 16, kb_ + (size_t)row * HS_ + sg * 4);
        cp16(vsa + row * 64 + sg * 16, vb_ + (size_t)row * HS_ + sg * 4);
    }
    CP_COMMIT();

    for (int it = 0; it < ntiles; ++it) {
        const int buf = it & 1;
        if (it + 1 < ntiles) {
            int kb2 = (it + 1) * 128;
            int ob = (buf ^ 1) * 8192;
            #pragma unroll
            for (int i = 0; i < 2; ++i) {
                int f = tid + i * 256;
                int row = f >> 2, sg = f & 3;
                cp16(ksa + ob + row * 64 + sg * 16, kb_ + (size_t)(kb2 + row) * HS_ + sg * 4);
                cp16(vsa + ob + row * 64 + sg * 16, vb_ + (size_t)(kb2 + row) * HS_ + sg * 4);
            }
        }
        CP_COMMIT();
        CP_WAIT1();
        __syncthreads();

        if (it < mytiles) {
            const int kbase = it * 128;
            #pragma unroll 2
            for (int j = 0; j < 128; ++j) {
                const float4* kr = (const float4*)&Ks[buf][j][0];
                float4 k0 = kr[0], k1 = kr[1], k2 = kr[2], k3 = kr[3];
                float sc = q0.x*k0.x + q0.y*k0.y + q0.z*k0.z + q0.w*k0.w
                         + q1.x*k1.x + q1.y*k1.y + q1.z*k1.z + q1.w*k1.w
                         + q2.x*k2.x + q2.y*k2.y + q2.z*k2.z + q2.w*k2.w
                         + q3.x*k3.x + q3.y*k3.y + q3.z*k3.z + q3.w*k3.w;
                sc *= ATT_SCALE;
                if (kbase + j > t) sc = -1e30f;
                float mn = fmaxf(m, sc);
                float scale = __expf(m - mn);
                float w = __expf(sc - mn);
                l = l * scale + w;
                const float4* vr = (const float4*)&Vs[buf][j][0];
                float4 v0 = vr[0], v1 = vr[1], v2 = vr[2], v3 = vr[3];
                o[0]  = o[0]*scale  + w*v0.x;  o[1]  = o[1]*scale  + w*v0.y;
                o[2]  = o[2]*scale  + w*v0.z;  o[3]  = o[3]*scale  + w*v0.w;
                o[4]  = o[4]*scale  + w*v1.x;  o[5]  = o[5]*scale  + w*v1.y;
                o[6]  = o[6]*scale  + w*v1.z;  o[7]  = o[7]*scale  + w*v1.w;
                o[8]  = o[8]*scale  + w*v2.x;  o[9]  = o[9]*scale  + w*v2.y;
                o[10] = o[10]*scale + w*v2.z;  o[11] = o[11]*scale + w*v2.w;
                o[12] = o[12]*scale + w*v3.x;  o[13] = o[13]*scale + w*v3.y;
                o[14] = o[14]*scale + w*v3.z;  o[15] = o[15]*scale + w*v3.w;
                m = mn;
            }
        }
        __syncthreads();
    }

    float inv = 1.0f / l;
    int b = bh >> 3, h = bh & 7;
    size_t base = ((size_t)b * T_ + t) * E_ + h * HS_;
    uint32_t hp[8];
    #pragma unroll
    for (int d = 0; d < 8; ++d)
        hp[d] = pack_f16(o[2 * d] * inv, o[2 * d + 1] * inv);
    ((uint4*)(aof + base))[0] = make_uint4(hp[0], hp[1], hp[2], hp[3]);
    ((uint4*)(aof + base))[1] = make_uint4(hp[4], hp[5], hp[6], hp[7]);
}

// ---------------------------------------------------------------------------
// O-proj fp16 1-pass, 32-token tiles (grid 128) + residual + fused LN2
// warp grid: 8 warps over N (16 cols each), all warps cover M=32
// ---------------------------------------------------------------------------
__global__ void __launch_bounds__(256, 1)
k_oproj_h32(const __half* __restrict__ af, const __half* __restrict__ wf,
            const float* __restrict__ bo, const float* __restrict__ x,
            const float* __restrict__ g2, const float* __restrict__ be2,
            float* __restrict__ x2, __half* __restrict__ h2f) {
    extern __shared__ char smem[];
    const uint32_t sb = smem_u32(smem);
    float* x2t = (float*)(smem + OQ_X2T);
    const int tid = threadIdx.x, wid = tid >> 5, lane = tid & 31;
    const int gid = lane >> 2, tig = lane & 3;
    const int lrow = (lane & 7) + ((lane >> 3) & 1) * 8;
    const int lcol = ((lane >> 4) & 1) * 8;
    const int tok0 = blockIdx.x * 32;
    const int n0 = wid * 16;

    for (int i = tid; i < 512; i += 256) {
        int r = i >> 4, s = i & 15;
        *(float4*)(smem + OQ_A + (r * SH + s * 8) * 2) =
            *(const float4*)(af + (size_t)(tok0 + r) * E_ + s * 8);
    }
    for (int i = tid; i < 2048; i += 256) {
        int r = i >> 4, s = i & 15;
        *(float4*)(smem + OQ_W + (r * SH + s * 8) * 2) =
            *(const float4*)(wf + (size_t)r * E_ + s * 8);
    }
    __syncthreads();

    float acc[2][2][4];
    #pragma unroll
    for (int a = 0; a < 2; ++a)
        #pragma unroll
        for (int b = 0; b < 2; ++b)
            #pragma unroll
            for (int c = 0; c < 4; ++c) acc[a][b][c] = 0.f;

    #pragma unroll
    for (int kf = 0; kf < 8; ++kf) {
        const int k0 = kf * 16;
        uint32_t afr[2][4], bq[4];
        #pragma unroll
        for (int mi = 0; mi < 2; ++mi) {
            uint32_t ro = (uint32_t)((mi * 16 + lrow) * SH + k0 + lcol) * 2;
            ldsm4(afr[mi], sb + OQ_A + ro);
        }
        {
            uint32_t ro = (uint32_t)((k0 + lrow) * SH + n0 + lcol) * 2;
            ldsm4t(bq, sb + OQ_W + ro);
        }
        #pragma unroll
        for (int mi = 0; mi < 2; ++mi)
            #pragma unroll
            for (int hh = 0; hh < 2; ++hh)
                mma16816h(acc[mi][hh], afr[mi], &bq[hh * 2]);
    }

    #pragma unroll
    for (int mi = 0; mi < 2; ++mi) {
        int rl = mi * 16 + gid;
        #pragma unroll
        for (int ni = 0; ni < 2; ++ni) {
            int col = n0 + ni * 8 + tig * 2;
            float2 bia = *(const float2*)(bo + col);
            float2 xr0 = *(const float2*)(x + (size_t)(tok0 + rl) * E_ + col);
            float2 xr1 = *(const float2*)(x + (size_t)(tok0 + rl + 8) * E_ + col);
            x2t[rl * 132 + col]           = acc[mi][ni][0] + bia.x + xr0.x;
            x2t[rl * 132 + col + 1]       = acc[mi][ni][1] + bia.y + xr0.y;
            x2t[(rl + 8) * 132 + col]     = acc[mi][ni][2] + bia.x + xr1.x;
            x2t[(rl + 8) * 132 + col + 1] = acc[mi][ni][3] + bia.y + xr1.y;
        }
    }
    __syncthreads();

    float4 gg = ((const float4*)g2)[lane];
    float4 bb = ((const float4*)be2)[lane];
    #pragma unroll
    for (int r = 0; r < 4; ++r) {
        int tokl = wid * 4 + r;
        float4 a = *(float4*)(x2t + tokl * 132 + lane * 4);
        float s = a.x + a.y + a.z + a.w;
        #pragma unroll
        for (int o = 16; o; o >>= 1) s += __shfl_xor_sync(0xffffffffu, s, o);
        float mu = s * (1.0f / E_);
        float dx = a.x - mu, dy = a.y - mu, dz = a.z - mu, dw = a.w - mu;
        float vv = dx*dx + dy*dy + dz*dz + dw*dw;
        #pragma unroll
        for (int o = 16; o; o >>= 1) vv += __shfl_xor_sync(0xffffffffu, vv, o);
        float rs = rsqrtf(vv * (1.0f / E_) + EPS_);

        ((float4*)(x2 + (size_t)(tok0 + tokl) * E_))[lane] = a;

        uint2 hp;
        hp.x = pack_f16(dx * rs * gg.x + bb.x, dy * rs * gg.y + bb.y);
        hp.y = pack_f16(dz * rs * gg.z + bb.z, dw * rs * gg.w + bb.w);
        ((uint2*)(h2f + (size_t)(tok0 + tokl) * E_))[lane] = hp;
    }
}

// ---------------------------------------------------------------------------
// FFN (R13 winner, frozen): fp16 1-pass, JC=64, 256 thr, 2 CTAs/SM
// ---------------------------------------------------------------------------
__global__ void __launch_bounds__(256, 2)
k_ffn4(const __half* __restrict__ h2,
       const __half* __restrict__ w1, const __half* __restrict__ w2,
       const float* __restrict__ bf1, float* __restrict__ partial) {
    extern __shared__ char smem[];
    const uint32_t sb = smem_u32(smem);
    const int tid = threadIdx.x, wid = tid >> 5, lane = tid & 31;
    const int gid = lane >> 2, tig = lane & 3;
    const int lrow = (lane & 7) + ((lane >> 3) & 1) * 8;
    const int lcol = ((lane >> 4) & 1) * 8;
    const int wm = wid & 3, wn = wid >> 2;
    const int m0 = wm * 32;
    const int cta = blockIdx.x;
    const int u0 = (int)(((long long)cta * TOT2) / FFN_GRID);
    const int u1 = (int)(((long long)(cta + 1) * TOT2) / FFN_GRID);

    {
        int jb = (u0 & (NCHUNK2 - 1)) * JC2;
        #pragma unroll
        for (int i = 0; i < 4; ++i) {
            int t = tid + i * 256;
            int e = t >> 3, sg = t & 7;
            cp16(sb + G3_W1 + (e * SWN + sg * 8) * 2, w1 + (size_t)e * HID_ + jb + sg * 8);
            int j = t >> 4, sg2 = t & 15;
            cp16(sb + G3_W2(0) + (j * SW2 + sg2 * 8) * 2, w2 + (size_t)(jb + j) * E_ + sg2 * 8);
        }
    }
    CP_COMMIT();

    int u = u0, seg = 0;
    while (u < u1) {
        const int tile = u >> 10;
        const int useg_end = min(u1, (tile + 1) << 10);
        const int tok0 = tile * FFN_M;

        for (int i = tid; i < 2048; i += 256) {
            int r = i >> 4, s = i & 15;
            *(float4*)(smem + G3_H + (r * SH + s * 8) * 2) =
                *(const float4*)(h2 + (size_t)(tok0 + r) * E_ + s * 8);
        }
        float acc2[2][8][4];
        #pragma unroll
        for (int a = 0; a < 2; ++a)
            #pragma unroll
            for (int b = 0; b < 8; ++b)
                #pragma unroll
                for (int c = 0; c < 4; ++c) acc2[a][b][c] = 0.f;
        __syncthreads();

        for (; u < useg_end; ++u) {
            const int buf = (u - u0) & 1;
            const int jb = (u & (NCHUNK2 - 1)) * JC2;
            const bool more = (u + 1 < u1);

            if (more) {
                int jn = ((u + 1) & (NCHUNK2 - 1)) * JC2;
                #pragma unroll
                for (int i = 0; i < 4; ++i) {
                    int t = tid + i * 256;
                    int j = t >> 4, sg2 = t & 15;
                    cp16(sb + G3_W2(buf ^ 1) + (j * SW2 + sg2 * 8) * 2,
                         w2 + (size_t)(jn + j) * E_ + sg2 * 8);
                }
                CP_COMMIT();
                CP_WAIT1();
            } else {
                CP_WAIT0();
            }
            __syncthreads();

            const int n1 = wn * 32;
            float acc1[2][4][4];
            #pragma unroll
            for (int a = 0; a < 2; ++a)
                #pragma unroll
                for (int b = 0; b < 4; ++b)
                    #pragma unroll
                    for (int d = 0; d < 4; ++d) acc1[a][b][d] = 0.f;

            #pragma unroll
            for (int kf = 0; kf < 8; ++kf) {
                const int k0 = kf * 16;
                uint32_t af[2][4], bq[2][4];
                #pragma unroll
                for (int mi = 0; mi < 2; ++mi) {
                    uint32_t ro = (uint32_t)((m0 + mi * 16 + lrow) * SH + k0 + lcol) * 2;
                    ldsm4(af[mi], sb + G3_H + ro);
                }
                #pragma unroll
                for (int g = 0; g < 2; ++g) {
                    uint32_t ro = (uint32_t)((k0 + lrow) * SWN + n1 + g * 16 + lcol) * 2;
                    ldsm4t(bq[g], sb + G3_W1 + ro);
                }
                #pragma unroll
                for (int mi = 0; mi < 2; ++mi)
                    #pragma unroll
                    for (int g = 0; g < 2; ++g)
                        #pragma unroll
                        for (int hh = 0; hh < 2; ++hh)
                            mma16816h(acc1[mi][g * 2 + hh], af[mi], &bq[g][hh * 2]);
            }

            #pragma unroll
            for (int ni = 0; ni < 4; ++ni) {
                const int col = n1 + ni * 8 + tig * 2;
                const float2 bia = *(const float2*)(bf1 + jb + col);
                #pragma unroll
                for (int mi = 0; mi < 2; ++mi) {
                    const int row = m0 + mi * 16 + gid;
                    float a0 = fmaxf(acc1[mi][ni][0] + bia.x, 0.f);
                    float a1 = fmaxf(acc1[mi][ni][1] + bia.y, 0.f);
                    float a2 = fmaxf(acc1[mi][ni][2] + bia.x, 0.f);
                    float a3 = fmaxf(acc1[mi][ni][3] + bia.y, 0.f);
                    *(uint32_t*)(smem + G3_AC + (uint32_t)(row * SWN + col) * 2) =
                        pack_f16(a0, a1);
                    *(uint32_t*)(smem + G3_AC + (uint32_t)((row + 8) * SWN + col) * 2) =
                        pack_f16(a2, a3);
                }
            }
            __syncthreads();

            if (more) {
                int jn = ((u + 1) & (NCHUNK2 - 1)) * JC2;
                #pragma unroll
                for (int i = 0; i < 4; ++i) {
                    int t = tid + i * 256;
                    int e = t >> 3, sg = t & 7;
                    cp16(sb + G3_W1 + (e * SWN + sg * 8) * 2,
                         w1 + (size_t)e * HID_ + jn + sg * 8);
                }
                CP_COMMIT();
            }

            const int n2 = wn * 64;
            #pragma unroll
            for (int kf = 0; kf < 4; ++kf) {
                const int k0 = kf * 16;
                uint32_t af[2][4], bq[4][4];
                #pragma unroll
                for (int mi = 0; mi < 2; ++mi) {
                    uint32_t ro = (uint32_t)((m0 + mi * 16 + lrow) * SWN + k0 + lcol) * 2;
                    ldsm4(af[mi], sb + G3_AC + ro);
                }
                #pragma unroll
                for (int nj = 0; nj < 4; ++nj) {
                    uint32_t ro = (uint32_t)((k0 + lrow) * SW2 + n2 + nj * 16 + lcol) * 2;
                    ldsm4t(bq[nj], sb + G3_W2(buf) + ro);
                }
                #pragma unroll
                for (int mi = 0; mi < 2; ++mi)
                    #pragma unroll
                    for (int nj = 0; nj < 4; ++nj)
                        #pragma unroll
                        for (int hh = 0; hh < 2; ++hh)
                            mma16816h(acc2[mi][nj * 2 + hh], af[mi], &bq[nj][hh * 2]);
            }
            __syncthreads();
        }

        {
            const int n2 = wn * 64;
            float* base = partial + ((size_t)(2 * cta + seg) << 14);
            #pragma unroll
            for (int mi = 0; mi < 2; ++mi) {
                const int row = m0 + mi * 16 + gid;
                #pragma unroll
                for (int nf = 0; nf < 8; ++nf) {
                    const int col = n2 + nf * 8 + tig * 2;
                    *(float2*)(base + row * E_ + col) =
                        make_float2(acc2[mi][nf][0], acc2[mi][nf][1]);
                    *(float2*)(base + (row + 8) * E_ + col) =
                        make_float2(acc2[mi][nf][2], acc2[mi][nf][3]);
                }
            }
        }
        seg++;
    }
}

// ---------------------------------------------------------------------------
// Final: out = x2 + bf2 + sum of covering partial slots
// ---------------------------------------------------------------------------
__global__ void k_final3(const float* __restrict__ x2, const float* __restrict__ partial,
                         const float* __restrict__ bf2, float* __restrict__ out) {
    int idx = blockIdx.x * blockDim.x + threadIdx.x;
    if (idx >= NTOK * E_) return;
    int e = idx & 127;
    int tok = idx >> 7;
    int t = tok >> 7;
    int row = tok & 127;

    int c_lo = (int)((((long long)t * 1024 + 1) * FFN_GRID - 1) >> 15);
    int c_hi = (int)((((long long)(t + 1) * 1024) * FFN_GRID - 1) >> 15);

    float s = x2[idx] + bf2[e];
    for (int c = c_lo; c <= c_hi; ++c) {
        int u0c = (int)(((long long)c << 15) / FFN_GRID);
        int seg = ((u0c >> 10) == t) ? 0 : 1;
        s += partial[((size_t)(2 * c + seg) << 14) + (row << 7) + e];
    }
    out[idx] = s;
}

// ---------------------------------------------------------------------------
// Launch: fork W1/W2 conversion onto a side stream, overlap attention path
// ---------------------------------------------------------------------------
extern "C" void kernel_launch(void* const* d_in, const int* in_sizes, int n_in,
                              void* d_out, int out_size) {
    const float* x   = (const float*)d_in[0];
    const float* Wk  = (const float*)d_in[1];
    const float* Wq  = (const float*)d_in[2];
    const float* Wv  = (const float*)d_in[3];
    const float* Wo  = (const float*)d_in[4];
    const float* bo  = (const float*)d_in[5];
    const float* g1  = (const float*)d_in[6];
    const float* be1 = (const float*)d_in[7];
    const float* g2  = (const float*)d_in[8];
    const float* be2 = (const float*)d_in[9];
    const float* W1  = (const float*)d_in[10];
    const float* bf1 = (const float*)d_in[11];
    const float* W2  = (const float*)d_in[12];
    const float* bf2 = (const float*)d_in[13];
    float* out = (float*)d_out;

    float *pq, *pk, *pv, *px2, *ppart;
    __half *ph1f, *paof, *ph2f, *pw1f, *pw2f, *pwqf, *pwof;
    cudaGetSymbolAddress((void**)&pq,    g_q);
    cudaGetSymbolAddress((void**)&pk,    g_k);
    cudaGetSymbolAddress((void**)&pv,    g_v);
    cudaGetSymbolAddress((void**)&px2,   g_x2);
    cudaGetSymbolAddress((void**)&ppart, g_part2);
    cudaGetSymbolAddress((void**)&ph1f,  g_h1f);
    cudaGetSymbolAddress((void**)&paof,  g_aof);
    cudaGetSymbolAddress((void**)&ph2f,  g_h2f);
    cudaGetSymbolAddress((void**)&pw1f,  g_w1f);
    cudaGetSymbolAddress((void**)&pw2f,  g_w2f);
    cudaGetSymbolAddress((void**)&pwqf,  g_wqkvf);
    cudaGetSymbolAddress((void**)&pwof,  g_wof);

    cudaFuncSetAttribute(k_ffn4, cudaFuncAttributeMaxDynamicSharedMemorySize, FFN_SMEM4);
    cudaFuncSetAttribute(k_qkv_h, cudaFuncAttributeMaxDynamicSharedMemorySize, QKV_SMEM_H);
    cudaFuncSetAttribute(k_oproj_h32, cudaFuncAttributeMaxDynamicSharedMemorySize, OP_SMEM2);

    // side stream + events for weight-prep overlap (created per call; not
    // destroyed — destroying capture-participating handles before EndCapture
    // would invalidate the harness's graph capture)
    cudaStream_t sprep;
    cudaEvent_t evFork, evJoin;
    bool forked = (cudaStreamCreateWithFlags(&sprep, cudaStreamNonBlocking) == cudaSuccess) &&
                  (cudaEventCreateWithFlags(&evFork, cudaEventDisableTiming) == cudaSuccess) &&
                  (cudaEventCreateWithFlags(&evJoin, cudaEventDisableTiming) == cudaSuccess);

    const int nW = E_ * HID_ / 4;

    if (forked && cudaEventRecord(evFork, 0) == cudaSuccess &&
        cudaStreamWaitEvent(sprep, evFork, 0) == cudaSuccess) {
        // FFN-only weight conversions on side stream (overlap attention path)
        k_cvthalf<<<(nW + 255) / 256, 256, 0, sprep>>>(W1, pw1f, nW);
        k_cvthalf<<<(nW + 255) / 256, 256, 0, sprep>>>(W2, pw2f, nW);
        cudaEventRecord(evJoin, sprep);
    } else {
        forked = false;
        k_cvthalf<<<(nW + 255) / 256, 256>>>(W1, pw1f, nW);
        k_cvthalf<<<(nW + 255) / 256, 256>>>(W2, pw2f, nW);
    }

    // early-needed small preps on main stream
    k_cvthalf<<<(E_ * E_ / 4 + 255) / 256, 256>>>(Wo, pwof, E_ * E_ / 4);
    k_prep_wqkv_h<<<(E_ * 384 + 255) / 256, 256>>>(Wq, Wk, Wv, pwqf);

    k_ln_half<<<NTOK / 4, 128>>>(x, g1, be1, ph1f);
    k_qkv_h<<<dim3(NTOK / 64, 3), 256, QKV_SMEM_H>>>(ph1f, pwqf, pq, pk, pv);
    k_attn2h<<<dim3(8, 16), 256>>>(pq, pk, pv, paof);
    k_oproj_h32<<<NTOK / 32, 256, OP_SMEM2>>>(paof, pwof, bo, x, g2, be2, px2, ph2f);

    if (forked) cudaStreamWaitEvent(0, evJoin, 0);
    k_ffn4<<<FFN_GRID, 256, FFN_SMEM4>>>(ph2f, pw1f, pw2f, bf1, ppart);
    k_final3<<<(NTOK * E_ + 255) / 256, 256>>>(px2, ppart, bf2, out);
}

// round 17
// speedup vs baseline: 1.3582x; 1.2602x over previous
#include <cuda_runtime.h>
#include <cuda_bf16.h>
#include <cuda_fp16.h>
#include <cstdint>
#include <math.h>

// ---------------------------------------------------------------------------
// Problem constants
// ---------------------------------------------------------------------------
#define B_  2
#define T_  2048
#define E_  128
#define H_  8
#define HS_ 16
#define HID_ 65536
#define NTOK (B_ * T_)          // 4096
#define EPS_ 1e-5f
#define ATT_SCALE 0.08838834764831845f   // 1/sqrt(128)

// FFN tiling (R13 winner, frozen)
#define FFN_M 128
#define JC2 64
#define NCHUNK2 (HID_ / JC2)        // 1024
#define NTILE (NTOK / FFN_M)        // 32
#define TOT2 (NTILE * NCHUNK2)      // 32768
#define FFN_GRID 888

#define SH   136
#define SWN  72
#define SW2  136

#define G3_H 0
#define G3_W1 34816
#define G3_W2(b) (53248 + (b) * 17408)
#define G3_AC 88064
#define FFN_SMEM4 106496

// QKV fp16 1-pass smem
#define GH_A 0
#define GH_W 17408
#define QKV_SMEM_H 52224

// O-proj 32-token tiles
#define OQ_A 0
#define OQ_W 8704
#define OQ_X2T 43520
#define OP_SMEM2 60416

// ---------------------------------------------------------------------------
// PTX helpers
// ---------------------------------------------------------------------------
__device__ __forceinline__ uint32_t smem_u32(const void* p) {
    uint32_t a;
    asm("{ .reg .u64 t; cvta.to.shared.u64 t, %1; cvt.u32.u64 %0, t; }"
        : "=r"(a) : "l"(p));
    return a;
}
__device__ __forceinline__ void ldsm4(uint32_t a[4], uint32_t addr) {
    asm volatile("ldmatrix.sync.aligned.m8n8.x4.shared.b16 {%0,%1,%2,%3}, [%4];"
                 : "=r"(a[0]), "=r"(a[1]), "=r"(a[2]), "=r"(a[3]) : "r"(addr));
}
__device__ __forceinline__ void ldsm4t(uint32_t a[4], uint32_t addr) {
    asm volatile("ldmatrix.sync.aligned.m8n8.x4.trans.shared.b16 {%0,%1,%2,%3}, [%4];"
                 : "=r"(a[0]), "=r"(a[1]), "=r"(a[2]), "=r"(a[3]) : "r"(addr));
}
__device__ __forceinline__ void mma16816h(float c[4], const uint32_t a[4],
                                          const uint32_t b[2]) {
    asm volatile("mma.sync.aligned.m16n8k16.row.col.f32.f16.f16.f32 "
                 "{%0,%1,%2,%3}, {%4,%5,%6,%7}, {%8,%9}, {%0,%1,%2,%3};"
                 : "+f"(c[0]), "+f"(c[1]), "+f"(c[2]), "+f"(c[3])
                 : "r"(a[0]), "r"(a[1]), "r"(a[2]), "r"(a[3]),
                   "r"(b[0]), "r"(b[1]));
}
__device__ __forceinline__ void mma16816h2(float c[4], const uint32_t a[4],
                                           uint32_t b0, uint32_t b1) {
    asm volatile("mma.sync.aligned.m16n8k16.row.col.f32.f16.f16.f32 "
                 "{%0,%1,%2,%3}, {%4,%5,%6,%7}, {%8,%9}, {%0,%1,%2,%3};"
                 : "+f"(c[0]), "+f"(c[1]), "+f"(c[2]), "+f"(c[3])
                 : "r"(a[0]), "r"(a[1]), "r"(a[2]), "r"(a[3]),
                   "r"(b0), "r"(b1));
}
__device__ __forceinline__ void cp16(uint32_t s, const void* g) {
    asm volatile("cp.async.cg.shared.global [%0], [%1], 16;" :: "r"(s), "l"(g));
}
#define CP_COMMIT() asm volatile("cp.async.commit_group;" ::: "memory")
#define CP_WAIT1()  asm volatile("cp.async.wait_group 1;" ::: "memory")
#define CP_WAIT0()  asm volatile("cp.async.wait_group 0;" ::: "memory")

__device__ __forceinline__ uint32_t pack_f16(float a, float b) {
    __half2 h = __floats2half2_rn(a, b);
    return *reinterpret_cast<uint32_t*>(&h);
}

// ---------------------------------------------------------------------------
// Scratch
// ---------------------------------------------------------------------------
__device__ __half g_qf [B_ * H_ * T_ * HS_];
__device__ __half g_kf [B_ * H_ * T_ * HS_];
__device__ __half g_vf [B_ * H_ * T_ * HS_];
__device__ float g_x2 [NTOK * E_];
__device__ float g_part2[2 * FFN_GRID * FFN_M * E_];
__device__ __half g_h1f [NTOK * E_];
__device__ __half g_aof [NTOK * E_];
__device__ __half g_h2f [NTOK * E_];
__device__ __half g_w1f [E_ * HID_];
__device__ __half g_w2f [HID_ * E_];
__device__ __half g_wqkvf[E_ * 384];
__device__ __half g_wof [E_ * E_];

// ---------------------------------------------------------------------------
// fp32 -> fp16 convert
// ---------------------------------------------------------------------------
__global__ void k_cvthalf(const float* __restrict__ src,
                          __half* __restrict__ dst, int n4) {
    int i = blockIdx.x * 256 + threadIdx.x;
    if (i >= n4) return;
    float4 v = ((const float4*)src)[i];
    uint2 o;
    o.x = pack_f16(v.x, v.y);
    o.y = pack_f16(v.z, v.w);
    ((uint2*)dst)[i] = o;
}

// Build Wqkv [E][384] fp16 from Wq/Wk/Wv [H][E][HS]
__global__ void k_prep_wqkv_h(const float* __restrict__ Wq, const float* __restrict__ Wk,
                              const float* __restrict__ Wv, __half* __restrict__ o) {
    int idx = blockIdx.x * 256 + threadIdx.x;
    if (idx >= E_ * 384) return;
    int e = idx / 384, n = idx % 384;
    int which = n >> 7, r = n & 127, h = r >> 4, hd = r & 15;
    const float* W = (which == 0) ? Wq : (which == 1) ? Wk : Wv;
    o[idx] = __float2half_rn(W[((size_t)h * E_ + e) * HS_ + hd]);
}

// ---------------------------------------------------------------------------
// LayerNorm with fp16 output (LN1)
// ---------------------------------------------------------------------------
__global__ void k_ln_half(const float* __restrict__ x, const float* __restrict__ g,
                          const float* __restrict__ b, __half* __restrict__ of) {
    int t = blockIdx.x * 4 + (threadIdx.x >> 5);
    int lane = threadIdx.x & 31;
    float4 a = ((const float4*)(x + (size_t)t * E_))[lane];

    float s = a.x + a.y + a.z + a.w;
    #pragma unroll
    for (int o = 16; o; o >>= 1) s += __shfl_xor_sync(0xffffffffu, s, o);
    float mu = s * (1.0f / E_);

    float dx = a.x - mu, dy = a.y - mu, dz = a.z - mu, dw = a.w - mu;
    float v = dx*dx + dy*dy + dz*dz + dw*dw;
    #pragma unroll
    for (int o = 16; o; o >>= 1) v += __shfl_xor_sync(0xffffffffu, v, o);
    float rs = rsqrtf(v * (1.0f / E_) + EPS_);

    float4 gg = ((const float4*)g)[lane];
    float4 bb = ((const float4*)b)[lane];
    uint2 hp;
    hp.x = pack_f16(dx * rs * gg.x + bb.x, dy * rs * gg.y + bb.y);
    hp.y = pack_f16(dz * rs * gg.z + bb.z, dw * rs * gg.w + bb.w);
    ((uint2*)(of + (size_t)t * E_))[lane] = hp;
}

// ---------------------------------------------------------------------------
// QKV via fp16 1-pass mma; outputs fp16 q (pre-scaled), k, v
// ---------------------------------------------------------------------------
__global__ void __launch_bounds__(256, 1)
k_qkv_h(const __half* __restrict__ af, const __half* __restrict__ wf,
        __half* __restrict__ q, __half* __restrict__ k, __half* __restrict__ v) {
    extern __shared__ char smem[];
    const uint32_t sb = smem_u32(smem);
    const int tid = threadIdx.x, wid = tid >> 5, lane = tid & 31;
    const int gid = lane >> 2, tig = lane & 3;
    const int lrow = (lane & 7) + ((lane >> 3) & 1) * 8;
    const int lcol = ((lane >> 4) & 1) * 8;
    const int wm = wid & 1, wn = wid >> 1;
    const int tok0 = blockIdx.x * 64;
    const int slab = blockIdx.y;
    const int m0 = wm * 32, n0 = wn * 32;

    for (int i = tid; i < 1024; i += 256) {
        int r = i >> 4, s = i & 15;
        *(float4*)(smem + GH_A + (r * SH + s * 8) * 2) =
            *(const float4*)(af + (size_t)(tok0 + r) * E_ + s * 8);
    }
    for (int i = tid; i < 2048; i += 256) {
        int r = i >> 4, s = i & 15;
        *(float4*)(smem + GH_W + (r * SH + s * 8) * 2) =
            *(const float4*)(wf + (size_t)r * 384 + slab * 128 + s * 8);
    }
    __syncthreads();

    float acc[2][4][4];
    #pragma unroll
    for (int a = 0; a < 2; ++a)
        #pragma unroll
        for (int b = 0; b < 4; ++b)
            #pragma unroll
            for (int c = 0; c < 4; ++c) acc[a][b][c] = 0.f;

    #pragma unroll
    for (int kf = 0; kf < 8; ++kf) {
        const int k0 = kf * 16;
        uint32_t afr[2][4], bq[2][4];
        #pragma unroll
        for (int mi = 0; mi < 2; ++mi) {
            uint32_t ro = (uint32_t)((m0 + mi * 16 + lrow) * SH + k0 + lcol) * 2;
            ldsm4(afr[mi], sb + GH_A + ro);
        }
        #pragma unroll
        for (int g = 0; g < 2; ++g) {
            uint32_t ro = (uint32_t)((k0 + lrow) * SH + n0 + g * 16 + lcol) * 2;
            ldsm4t(bq[g], sb + GH_W + ro);
        }
        #pragma unroll
        for (int mi = 0; mi < 2; ++mi)
            #pragma unroll
            for (int g = 0; g < 2; ++g)
                #pragma unroll
                for (int hh = 0; hh < 2; ++hh)
                    mma16816h(acc[mi][g * 2 + hh], afr[mi], &bq[g][hh * 2]);
    }

    __half* dst = (slab == 0) ? q : (slab == 1) ? k : v;
    const float scv = (slab == 0) ? ATT_SCALE : 1.0f;
    #pragma unroll
    for (int mi = 0; mi < 2; ++mi) {
        int tg = tok0 + m0 + mi * 16 + gid;
        int b = tg >> 11, tl = tg & 2047;
        #pragma unroll
        for (int ni = 0; ni < 4; ++ni) {
            int n = n0 + ni * 8 + tig * 2;
            int h = n >> 4, hd = n & 15;
            __half* p = dst + (((size_t)(b * 8 + h)) * T_ + tl) * HS_ + hd;
            *(uint32_t*)p = pack_f16(acc[mi][ni][0] * scv, acc[mi][ni][1] * scv);
            *(uint32_t*)(p + 8 * HS_) = pack_f16(acc[mi][ni][2] * scv, acc[mi][ni][3] * scv);
        }
    }
}

// ---------------------------------------------------------------------------
// Attention v5: tensor-core flash attention, R13 pairing skeleton.
// grid (8,16), 256 thr. Warp handles 32 queries x 128-key tiles via mma.
// ---------------------------------------------------------------------------
__global__ void __launch_bounds__(256, 1)
k_attn5(const __half* __restrict__ qf, const __half* __restrict__ kf,
        const __half* __restrict__ vf, __half* __restrict__ aof) {
    __shared__ __half Qs[2][128][16];
    __shared__ __half Ks[2][128][16];
    __shared__ __half Vs[2][128][16];
    const int tid = threadIdx.x, wid = tid >> 5, lane = tid & 31;
    const int bh = blockIdx.y, qb = blockIdx.x;
    const int wg = wid >> 2, g = wid & 3;
    const int qblk = wg ? (15 - qb) : qb;
    const int mytiles = qblk + 1;
    const int ntiles = 16 - qb;
    const int gid = lane >> 2, tig = lane & 3;
    const int lrow = (lane & 7) + ((lane >> 3) & 1) * 8;
    const int lcol = ((lane >> 4) & 1) * 8;

    const __half* kb_ = kf + (size_t)bh * T_ * HS_;
    const __half* vb_ = vf + (size_t)bh * T_ * HS_;
    const uint32_t qsa = smem_u32(Qs), ksa = smem_u32(Ks), vsa = smem_u32(Vs);

    // stage Q (both paired blocks) + K/V tile 0 — group 0
    {
        const __half* qb_ = qf + (size_t)bh * T_ * HS_;
        #pragma unroll
        for (int i = 0; i < 2; ++i) {
            int blkw = i;                     // tid covers 256 chunks per block
            int qblk_w = blkw ? (15 - qb) : qb;
            cp16(qsa + (uint32_t)(blkw * 4096 + tid * 16),
                 qb_ + (size_t)qblk_w * 128 * HS_ + tid * 8);
        }
        cp16(ksa + tid * 16, kb_ + tid * 8);
        cp16(vsa + tid * 16, vb_ + tid * 8);
    }
    CP_COMMIT();

    float mrun[2][2], lrun[2][2], o[2][2][4];
    #pragma unroll
    for (int mi = 0; mi < 2; ++mi)
        #pragma unroll
        for (int h = 0; h < 2; ++h) {
            mrun[mi][h] = -1e30f; lrun[mi][h] = 0.f;
            o[mi][0][2 * h] = 0.f; o[mi][0][2 * h + 1] = 0.f;
            o[mi][1][2 * h] = 0.f; o[mi][1][2 * h + 1] = 0.f;
        }
    uint32_t qa[2][4];

    for (int it = 0; it < ntiles; ++it) {
        const int buf = it & 1;
        if (it + 1 < ntiles) {
            uint32_t ob = (uint32_t)(buf ^ 1) * 4096;
            const size_t goff = (size_t)(it + 1) * 128 * HS_ + tid * 8;
            cp16(ksa + ob + tid * 16, kb_ + goff);
            cp16(vsa + ob + tid * 16, vb_ + goff);
        }
        CP_COMMIT();
        CP_WAIT1();
        __syncthreads();

        if (it == 0) {
            // load persistent Q fragments (own block, own 32-query group)
            #pragma unroll
            for (int mi = 0; mi < 2; ++mi)
                ldsm4(qa[mi], qsa + (uint32_t)(wg * 4096 +
                      ((g * 32 + mi * 16 + lrow) * 16 + lcol) * 2));
        }

        if (it < mytiles) {
            const bool diag = (it == qblk);
            const int cmax = diag ? (g + 1) : 4;
            const uint32_t kb2 = (uint32_t)buf * 4096;
            for (int ck = 0; ck < cmax; ++ck) {
                const bool maskck = diag && (ck == g);
                // K fragments (32 keys)
                uint32_t kr0[4], kr1[4];
                ldsm4(kr0, ksa + kb2 + (uint32_t)(((ck * 32 + lrow) * 16 + lcol) * 2));
                ldsm4(kr1, ksa + kb2 + (uint32_t)(((ck * 32 + 16 + lrow) * 16 + lcol) * 2));

                // S = Q K^T
                float s[2][4][4];
                #pragma unroll
                for (int mi = 0; mi < 2; ++mi)
                    #pragma unroll
                    for (int nj = 0; nj < 4; ++nj) {
                        #pragma unroll
                        for (int e = 0; e < 4; ++e) s[mi][nj][e] = 0.f;
                        const uint32_t* kr = (nj < 2) ? kr0 : kr1;
                        int pair = nj & 1;
                        mma16816h2(s[mi][nj], qa[mi], kr[pair], kr[pair + 2]);
                    }

                // causal mask (diagonal sub-chunk only)
                if (maskck) {
                    #pragma unroll
                    for (int mi = 0; mi < 2; ++mi)
                        #pragma unroll
                        for (int nj = 0; nj < 4; ++nj)
                            #pragma unroll
                            for (int e = 0; e < 4; ++e) {
                                int col = nj * 8 + tig * 2 + (e & 1);
                                int row = mi * 16 + gid + ((e >> 1) * 8);
                                if (col > row) s[mi][nj][e] = -1e30f;
                            }
                }

                // online softmax (row stats over tig quad)
                #pragma unroll
                for (int mi = 0; mi < 2; ++mi)
                    #pragma unroll
                    for (int h = 0; h < 2; ++h) {
                        float cm = -1e30f;
                        #pragma unroll
                        for (int nj = 0; nj < 4; ++nj) {
                            cm = fmaxf(cm, s[mi][nj][2 * h]);
                            cm = fmaxf(cm, s[mi][nj][2 * h + 1]);
                        }
                        cm = fmaxf(cm, __shfl_xor_sync(0xffffffffu, cm, 1));
                        cm = fmaxf(cm, __shfl_xor_sync(0xffffffffu, cm, 2));
                        float mn = fmaxf(mrun[mi][h], cm);
                        float sc2 = __expf(mrun[mi][h] - mn);
                        mrun[mi][h] = mn;
                        lrun[mi][h] *= sc2;
                        o[mi][0][2 * h] *= sc2; o[mi][0][2 * h + 1] *= sc2;
                        o[mi][1][2 * h] *= sc2; o[mi][1][2 * h + 1] *= sc2;
                        float ls = 0.f;
                        #pragma unroll
                        for (int nj = 0; nj < 4; ++nj) {
                            float p0 = __expf(s[mi][nj][2 * h] - mn);
                            float p1 = __expf(s[mi][nj][2 * h + 1] - mn);
                            s[mi][nj][2 * h] = p0; s[mi][nj][2 * h + 1] = p1;
                            ls += p0 + p1;
                        }
                        lrun[mi][h] += ls;   // lane-partial; reduced at end
                    }

                // V fragments and P@V
                uint32_t vr0[4], vr1[4];
                ldsm4t(vr0, vsa + kb2 + (uint32_t)(((ck * 32 + lrow) * 16 + lcol) * 2));
                ldsm4t(vr1, vsa + kb2 + (uint32_t)(((ck * 32 + 16 + lrow) * 16 + lcol) * 2));
                #pragma unroll
                for (int mi = 0; mi < 2; ++mi) {
                    uint32_t pa0[4], pa1[4];
                    pa0[0] = pack_f16(s[mi][0][0], s[mi][0][1]);
                    pa0[1] = pack_f16(s[mi][0][2], s[mi][0][3]);
                    pa0[2] = pack_f16(s[mi][1][0], s[mi][1][1]);
                    pa0[3] = pack_f16(s[mi][1][2], s[mi][1][3]);
                    pa1[0] = pack_f16(s[mi][2][0], s[mi][2][1]);
                    pa1[1] = pack_f16(s[mi][2][2], s[mi][2][3]);
                    pa1[2] = pack_f16(s[mi][3][0], s[mi][3][1]);
                    pa1[3] = pack_f16(s[mi][3][2], s[mi][3][3]);
                    #pragma unroll
                    for (int nj = 0; nj < 2; ++nj) {
                        mma16816h(o[mi][nj], pa0, &vr0[nj * 2]);
                        mma16816h(o[mi][nj], pa1, &vr1[nj * 2]);
                    }
                }
            }
        }
        __syncthreads();
    }

    // epilogue: reduce l over quad, normalize, write fp16
    const int b = bh >> 3, head = bh & 7;
    #pragma unroll
    for (int mi = 0; mi < 2; ++mi)
        #pragma unroll
        for (int h = 0; h < 2; ++h) {
            float l = lrun[mi][h];
            l += __shfl_xor_sync(0xffffffffu, l, 1);
            l += __shfl_xor_sync(0xffffffffu, l, 2);
            float inv = 1.0f / l;
            int t = qblk * 128 + g * 32 + mi * 16 + gid + h * 8;
            size_t base = ((size_t)b * T_ + t) * E_ + head * HS_;
            *(uint32_t*)(aof + base + tig * 2) =
                pack_f16(o[mi][0][2 * h] * inv, o[mi][0][2 * h + 1] * inv);
            *(uint32_t*)(aof + base + 8 + tig * 2) =
                pack_f16(o[mi][1][2 * h] * inv, o[mi][1][2 * h + 1] * inv);
        }
}

// ---------------------------------------------------------------------------
// O-proj fp16 1-pass, 32-token tiles + residual + fused LN2
// ---------------------------------------------------------------------------
__global__ void __launch_bounds__(256, 1)
k_oproj_h32(const __half* __restrict__ af, const __half* __restrict__ wf,
            const float* __restrict__ bo, const float* __restrict__ x,
            const float* __restrict__ g2, const float* __restrict__ be2,
            float* __restrict__ x2, __half* __restrict__ h2f) {
    extern __shared__ char smem[];
    const uint32_t sb = smem_u32(smem);
    float* x2t = (float*)(smem + OQ_X2T);
    const int tid = threadIdx.x, wid = tid >> 5, lane = tid & 31;
    const int gid = lane >> 2, tig = lane & 3;
    const int lrow = (lane & 7) + ((lane >> 3) & 1) * 8;
    const int lcol = ((lane >> 4) & 1) * 8;
    const int tok0 = blockIdx.x * 32;
    const int n0 = wid * 16;

    for (int i = tid; i < 512; i += 256) {
        int r = i >> 4, s = i & 15;
        *(float4*)(smem + OQ_A + (r * SH + s * 8) * 2) =
            *(const float4*)(af + (size_t)(tok0 + r) * E_ + s * 8);
    }
    for (int i = tid; i < 2048; i += 256) {
        int r = i >> 4, s = i & 15;
        *(float4*)(smem + OQ_W + (r * SH + s * 8) * 2) =
            *(const float4*)(wf + (size_t)r * E_ + s * 8);
    }
    __syncthreads();

    float acc[2][2][4];
    #pragma unroll
    for (int a = 0; a < 2; ++a)
        #pragma unroll
        for (int b = 0; b < 2; ++b)
            #pragma unroll
            for (int c = 0; c < 4; ++c) acc[a][b][c] = 0.f;

    #pragma unroll
    for (int kf = 0; kf < 8; ++kf) {
        const int k0 = kf * 16;
        uint32_t afr[2][4], bq[4];
        #pragma unroll
        for (int mi = 0; mi < 2; ++mi) {
            uint32_t ro = (uint32_t)((mi * 16 + lrow) * SH + k0 + lcol) * 2;
            ldsm4(afr[mi], sb + OQ_A + ro);
        }
        {
            uint32_t ro = (uint32_t)((k0 + lrow) * SH + n0 + lcol) * 2;
            ldsm4t(bq, sb + OQ_W + ro);
        }
        #pragma unroll
        for (int mi = 0; mi < 2; ++mi)
            #pragma unroll
            for (int hh = 0; hh < 2; ++hh)
                mma16816h(acc[mi][hh], afr[mi], &bq[hh * 2]);
    }

    #pragma unroll
    for (int mi = 0; mi < 2; ++mi) {
        int rl = mi * 16 + gid;
        #pragma unroll
        for (int ni = 0; ni < 2; ++ni) {
            int col = n0 + ni * 8 + tig * 2;
            float2 bia = *(const float2*)(bo + col);
            float2 xr0 = *(const float2*)(x + (size_t)(tok0 + rl) * E_ + col);
            float2 xr1 = *(const float2*)(x + (size_t)(tok0 + rl + 8) * E_ + col);
            x2t[rl * 132 + col]           = acc[mi][ni][0] + bia.x + xr0.x;
            x2t[rl * 132 + col + 1]       = acc[mi][ni][1] + bia.y + xr0.y;
            x2t[(rl + 8) * 132 + col]     = acc[mi][ni][2] + bia.x + xr1.x;
            x2t[(rl + 8) * 132 + col + 1] = acc[mi][ni][3] + bia.y + xr1.y;
        }
    }
    __syncthreads();

    float4 gg = ((const float4*)g2)[lane];
    float4 bb = ((const float4*)be2)[lane];
    #pragma unroll
    for (int r = 0; r < 4; ++r) {
        int tokl = wid * 4 + r;
        float4 a = *(float4*)(x2t + tokl * 132 + lane * 4);
        float s = a.x + a.y + a.z + a.w;
        #pragma unroll
        for (int o = 16; o; o >>= 1) s += __shfl_xor_sync(0xffffffffu, s, o);
        float mu = s * (1.0f / E_);
        float dx = a.x - mu, dy = a.y - mu, dz = a.z - mu, dw = a.w - mu;
        float vv = dx*dx + dy*dy + dz*dz + dw*dw;
        #pragma unroll
        for (int o = 16; o; o >>= 1) vv += __shfl_xor_sync(0xffffffffu, vv, o);
        float rs = rsqrtf(vv * (1.0f / E_) + EPS_);

        ((float4*)(x2 + (size_t)(tok0 + tokl) * E_))[lane] = a;

        uint2 hp;
        hp.x = pack_f16(dx * rs * gg.x + bb.x, dy * rs * gg.y + bb.y);
        hp.y = pack_f16(dz * rs * gg.z + bb.z, dw * rs * gg.w + bb.w);
        ((uint2*)(h2f + (size_t)(tok0 + tokl) * E_))[lane] = hp;
    }
}

// ---------------------------------------------------------------------------
// FFN (R13 winner, frozen)
// ---------------------------------------------------------------------------
__global__ void __launch_bounds__(256, 2)
k_ffn4(const __half* __restrict__ h2,
       const __half* __restrict__ w1, const __half* __restrict__ w2,
       const float* __restrict__ bf1, float* __restrict__ partial) {
    extern __shared__ char smem[];
    const uint32_t sb = smem_u32(smem);
    const int tid = threadIdx.x, wid = tid >> 5, lane = tid & 31;
    const int gid = lane >> 2, tig = lane & 3;
    const int lrow = (lane & 7) + ((lane >> 3) & 1) * 8;
    const int lcol = ((lane >> 4) & 1) * 8;
    const int wm = wid & 3, wn = wid >> 2;
    const int m0 = wm * 32;
    const int cta = blockIdx.x;
    const int u0 = (int)(((long long)cta * TOT2) / FFN_GRID);
    const int u1 = (int)(((long long)(cta + 1) * TOT2) / FFN_GRID);

    {
        int jb = (u0 & (NCHUNK2 - 1)) * JC2;
        #pragma unroll
        for (int i = 0; i < 4; ++i) {
            int t = tid + i * 256;
            int e = t >> 3, sg = t & 7;
            cp16(sb + G3_W1 + (e * SWN + sg * 8) * 2, w1 + (size_t)e * HID_ + jb + sg * 8);
            int j = t >> 4, sg2 = t & 15;
            cp16(sb + G3_W2(0) + (j * SW2 + sg2 * 8) * 2, w2 + (size_t)(jb + j) * E_ + sg2 * 8);
        }
    }
    CP_COMMIT();

    int u = u0, seg = 0;
    while (u < u1) {
        const int tile = u >> 10;
        const int useg_end = min(u1, (tile + 1) << 10);
        const int tok0 = tile * FFN_M;

        for (int i = tid; i < 2048; i += 256) {
            int r = i >> 4, s = i & 15;
            *(float4*)(smem + G3_H + (r * SH + s * 8) * 2) =
                *(const float4*)(h2 + (size_t)(tok0 + r) * E_ + s * 8);
        }
        float acc2[2][8][4];
        #pragma unroll
        for (int a = 0; a < 2; ++a)
            #pragma unroll
            for (int b = 0; b < 8; ++b)
                #pragma unroll
                for (int c = 0; c < 4; ++c) acc2[a][b][c] = 0.f;
        __syncthreads();

        for (; u < useg_end; ++u) {
            const int buf = (u - u0) & 1;
            const int jb = (u & (NCHUNK2 - 1)) * JC2;
            const bool more = (u + 1 < u1);

            if (more) {
                int jn = ((u + 1) & (NCHUNK2 - 1)) * JC2;
                #pragma unroll
                for (int i = 0; i < 4; ++i) {
                    int t = tid + i * 256;
                    int j = t >> 4, sg2 = t & 15;
                    cp16(sb + G3_W2(buf ^ 1) + (j * SW2 + sg2 * 8) * 2,
                         w2 + (size_t)(jn + j) * E_ + sg2 * 8);
                }
                CP_COMMIT();
                CP_WAIT1();
            } else {
                CP_WAIT0();
            }
            __syncthreads();

            const int n1 = wn * 32;
            float acc1[2][4][4];
            #pragma unroll
            for (int a = 0; a < 2; ++a)
                #pragma unroll
                for (int b = 0; b < 4; ++b)
                    #pragma unroll
                    for (int d = 0; d < 4; ++d) acc1[a][b][d] = 0.f;

            #pragma unroll
            for (int kf = 0; kf < 8; ++kf) {
                const int k0 = kf * 16;
                uint32_t af[2][4], bq[2][4];
                #pragma unroll
                for (int mi = 0; mi < 2; ++mi) {
                    uint32_t ro = (uint32_t)((m0 + mi * 16 + lrow) * SH + k0 + lcol) * 2;
                    ldsm4(af[mi], sb + G3_H + ro);
                }
                #pragma unroll
                for (int g = 0; g < 2; ++g) {
                    uint32_t ro = (uint32_t)((k0 + lrow) * SWN + n1 + g * 16 + lcol) * 2;
                    ldsm4t(bq[g], sb + G3_W1 + ro);
                }
                #pragma unroll
                for (int mi = 0; mi < 2; ++mi)
                    #pragma unroll
                    for (int g = 0; g < 2; ++g)
                        #pragma unroll
                        for (int hh = 0; hh < 2; ++hh)
                            mma16816h(acc1[mi][g * 2 + hh], af[mi], &bq[g][hh * 2]);
            }

            #pragma unroll
            for (int ni = 0; ni < 4; ++ni) {
                const int col = n1 + ni * 8 + tig * 2;
                const float2 bia = *(const float2*)(bf1 + jb + col);
                #pragma unroll
                for (int mi = 0; mi < 2; ++mi) {
                    const int row = m0 + mi * 16 + gid;
                    float a0 = fmaxf(acc1[mi][ni][0] + bia.x, 0.f);
                    float a1 = fmaxf(acc1[mi][ni][1] + bia.y, 0.f);
                    float a2 = fmaxf(acc1[mi][ni][2] + bia.x, 0.f);
                    float a3 = fmaxf(acc1[mi][ni][3] + bia.y, 0.f);
                    *(uint32_t*)(smem + G3_AC + (uint32_t)(row * SWN + col) * 2) =
                        pack_f16(a0, a1);
                    *(uint32_t*)(smem + G3_AC + (uint32_t)((row + 8) * SWN + col) * 2) =
                        pack_f16(a2, a3);
                }
            }
            __syncthreads();

            if (more) {
                int jn = ((u + 1) & (NCHUNK2 - 1)) * JC2;
                #pragma unroll
                for (int i = 0; i < 4; ++i) {
                    int t = tid + i * 256;
                    int e = t >> 3, sg = t & 7;
                    cp16(sb + G3_W1 + (e * SWN + sg * 8) * 2,
                         w1 + (size_t)e * HID_ + jn + sg * 8);
                }
                CP_COMMIT();
            }

            const int n2 = wn * 64;
            #pragma unroll
            for (int kf = 0; kf < 4; ++kf) {
                const int k0 = kf * 16;
                uint32_t af[2][4], bq[4][4];
                #pragma unroll
                for (int mi = 0; mi < 2; ++mi) {
                    uint32_t ro = (uint32_t)((m0 + mi * 16 + lrow) * SWN + k0 + lcol) * 2;
                    ldsm4(af[mi], sb + G3_AC + ro);
                }
                #pragma unroll
                for (int nj = 0; nj < 4; ++nj) {
                    uint32_t ro = (uint32_t)((k0 + lrow) * SW2 + n2 + nj * 16 + lcol) * 2;
                    ldsm4t(bq[nj], sb + G3_W2(buf) + ro);
                }
                #pragma unroll
                for (int mi = 0; mi < 2; ++mi)
                    #pragma unroll
                    for (int nj = 0; nj < 4; ++nj)
                        #pragma unroll
                        for (int hh = 0; hh < 2; ++hh)
                            mma16816h(acc2[mi][nj * 2 + hh], af[mi], &bq[nj][hh * 2]);
            }
            __syncthreads();
        }

        {
            const int n2 = wn * 64;
            float* base = partial + ((size_t)(2 * cta + seg) << 14);
            #pragma unroll
            for (int mi = 0; mi < 2; ++mi) {
                const int row = m0 + mi * 16 + gid;
                #pragma unroll
                for (int nf = 0; nf < 8; ++nf) {
                    const int col = n2 + nf * 8 + tig * 2;
                    *(float2*)(base + row * E_ + col) =
                        make_float2(acc2[mi][nf][0], acc2[mi][nf][1]);
                    *(float2*)(base + (row + 8) * E_ + col) =
                        make_float2(acc2[mi][nf][2], acc2[mi][nf][3]);
                }
            }
        }
        seg++;
    }
}

// ---------------------------------------------------------------------------
// Final: out = x2 + bf2 + sum of covering partial slots
// ---------------------------------------------------------------------------
__global__ void k_final3(const float* __restrict__ x2, const float* __restrict__ partial,
                         const float* __restrict__ bf2, float* __restrict__ out) {
    int idx = blockIdx.x * blockDim.x + threadIdx.x;
    if (idx >= NTOK * E_) return;
    int e = idx & 127;
    int tok = idx >> 7;
    int t = tok >> 7;
    int row = tok & 127;

    int c_lo = (int)((((long long)t * 1024 + 1) * FFN_GRID - 1) >> 15);
    int c_hi = (int)((((long long)(t + 1) * 1024) * FFN_GRID - 1) >> 15);

    float s = x2[idx] + bf2[e];
    for (int c = c_lo; c <= c_hi; ++c) {
        int u0c = (int)(((long long)c << 15) / FFN_GRID);
        int seg = ((u0c >> 10) == t) ? 0 : 1;
        s += partial[((size_t)(2 * c + seg) << 14) + (row << 7) + e];
    }
    out[idx] = s;
}

// ---------------------------------------------------------------------------
// Launch
// ---------------------------------------------------------------------------
extern "C" void kernel_launch(void* const* d_in, const int* in_sizes, int n_in,
                              void* d_out, int out_size) {
    const float* x   = (const float*)d_in[0];
    const float* Wk  = (const float*)d_in[1];
    const float* Wq  = (const float*)d_in[2];
    const float* Wv  = (const float*)d_in[3];
    const float* Wo  = (const float*)d_in[4];
    const float* bo  = (const float*)d_in[5];
    const float* g1  = (const float*)d_in[6];
    const float* be1 = (const float*)d_in[7];
    const float* g2  = (const float*)d_in[8];
    const float* be2 = (const float*)d_in[9];
    const float* W1  = (const float*)d_in[10];
    const float* bf1 = (const float*)d_in[11];
    const float* W2  = (const float*)d_in[12];
    const float* bf2 = (const float*)d_in[13];
    float* out = (float*)d_out;

    float *px2, *ppart;
    __half *pqf, *pkf, *pvf, *ph1f, *paof, *ph2f, *pw1f, *pw2f, *pwqf, *pwof;
    cudaGetSymbolAddress((void**)&pqf,   g_qf);
    cudaGetSymbolAddress((void**)&pkf,   g_kf);
    cudaGetSymbolAddress((void**)&pvf,   g_vf);
    cudaGetSymbolAddress((void**)&px2,   g_x2);
    cudaGetSymbolAddress((void**)&ppart, g_part2);
    cudaGetSymbolAddress((void**)&ph1f,  g_h1f);
    cudaGetSymbolAddress((void**)&paof,  g_aof);
    cudaGetSymbolAddress((void**)&ph2f,  g_h2f);
    cudaGetSymbolAddress((void**)&pw1f,  g_w1f);
    cudaGetSymbolAddress((void**)&pw2f,  g_w2f);
    cudaGetSymbolAddress((void**)&pwqf,  g_wqkvf);
    cudaGetSymbolAddress((void**)&pwof,  g_wof);

    cudaFuncSetAttribute(k_ffn4, cudaFuncAttributeMaxDynamicSharedMemorySize, FFN_SMEM4);
    cudaFuncSetAttribute(k_qkv_h, cudaFuncAttributeMaxDynamicSharedMemorySize, QKV_SMEM_H);
    cudaFuncSetAttribute(k_oproj_h32, cudaFuncAttributeMaxDynamicSharedMemorySize, OP_SMEM2);

    // side stream + events for weight-prep overlap (handles not destroyed:
    // destroying capture-participating handles would invalidate graph capture)
    cudaStream_t sprep;
    cudaEvent_t evFork, evJoin;
    bool forked = (cudaStreamCreateWithFlags(&sprep, cudaStreamNonBlocking) == cudaSuccess) &&
                  (cudaEventCreateWithFlags(&evFork, cudaEventDisableTiming) == cudaSuccess) &&
                  (cudaEventCreateWithFlags(&evJoin, cudaEventDisableTiming) == cudaSuccess);

    const int nW = E_ * HID_ / 4;

    if (forked && cudaEventRecord(evFork, 0) == cudaSuccess &&
        cudaStreamWaitEvent(sprep, evFork, 0) == cudaSuccess) {
        k_cvthalf<<<(nW + 255) / 256, 256, 0, sprep>>>(W1, pw1f, nW);
        k_cvthalf<<<(nW + 255) / 256, 256, 0, sprep>>>(W2, pw2f, nW);
        cudaEventRecord(evJoin, sprep);
    } else {
        forked = false;
        k_cvthalf<<<(nW + 255) / 256, 256>>>(W1, pw1f, nW);
        k_cvthalf<<<(nW + 255) / 256, 256>>>(W2, pw2f, nW);
    }

    k_cvthalf<<<(E_ * E_ / 4 + 255) / 256, 256>>>(Wo, pwof, E_ * E_ / 4);
    k_prep_wqkv_h<<<(E_ * 384 + 255) / 256, 256>>>(Wq, Wk, Wv, pwqf);

    k_ln_half<<<NTOK / 4, 128>>>(x, g1, be1, ph1f);
    k_qkv_h<<<dim3(NTOK / 64, 3), 256, QKV_SMEM_H>>>(ph1f, pwqf, pqf, pkf, pvf);
    k_attn5<<<dim3(8, 16), 256>>>(pqf, pkf, pvf, paof);
    k_oproj_h32<<<NTOK / 32, 256, OP_SMEM2>>>(paof, pwof, bo, x, g2, be2, px2, ph2f);

    if (forked) cudaStreamWaitEvent(0, evJoin, 0);
    k_ffn4<<<FFN_GRID, 256, FFN_SMEM4>>>(ph2f, pw1f, pw2f, bf1, ppart);
    k_final3<<<(NTOK * E_ + 255) / 256, 256>>>(px2, ppart, bf2, out);
}